// round 1
// baseline (speedup 1.0000x reference)
#include <cuda_runtime.h>
#include <math.h>

#define N_NODES 4096
#define NFEAT   1024
#define NHID    128
#define NHEADS  8
#define NCLASS  64
#define ALPHA_LRELU 0.2f
#define NEG_INF_F (-9e15f)

// ---------------- scratch (static device globals; no allocation) ----------------
__device__ float g_Wh[NHEADS * N_NODES * NHID];        // 16 MB
__device__ float g_f1[NHEADS * N_NODES];
__device__ float g_f2[NHEADS * N_NODES];
__device__ float g_hcat[N_NODES * NHEADS * NHID];      // 16 MB, [n][h*128+d]
__device__ float g_Who[N_NODES * NCLASS];              // 1 MB
__device__ float g_g1[N_NODES];
__device__ float g_g2[N_NODES];

// ---------------- K1: Wh[h] = x @ W[h]  (128x128x8 tiled SGEMM) ----------------
__global__ __launch_bounds__(256) void wh_gemm(const float* __restrict__ x,
                                               const float* __restrict__ W) {
    const int h  = blockIdx.y;
    const int m0 = blockIdx.x * 128;
    const float* B = W + (size_t)h * NFEAT * NHID;          // [1024,128]
    float* C = g_Wh + (size_t)h * N_NODES * NHID;           // [4096,128]

    __shared__ float As[8][128];
    __shared__ float Bs[8][128];

    const int tid = threadIdx.x;
    const int tr = tid >> 4, tc = tid & 15;
    const int arow = tid >> 1, akq = (tid & 1) * 4;
    const int bk = tid >> 5, bn = (tid & 31) * 4;

    float acc[8][8];
    #pragma unroll
    for (int i = 0; i < 8; i++)
        #pragma unroll
        for (int j = 0; j < 8; j++) acc[i][j] = 0.f;

    for (int k0 = 0; k0 < NFEAT; k0 += 8) {
        float4 av = *(const float4*)(x + (size_t)(m0 + arow) * NFEAT + k0 + akq);
        As[akq + 0][arow] = av.x;
        As[akq + 1][arow] = av.y;
        As[akq + 2][arow] = av.z;
        As[akq + 3][arow] = av.w;
        *(float4*)&Bs[bk][bn] = *(const float4*)(B + (size_t)(k0 + bk) * NHID + bn);
        __syncthreads();
        #pragma unroll
        for (int k = 0; k < 8; k++) {
            float a[8], b[8];
            *(float4*)&a[0] = *(float4*)&As[k][tr * 8];
            *(float4*)&a[4] = *(float4*)&As[k][tr * 8 + 4];
            *(float4*)&b[0] = *(float4*)&Bs[k][tc * 8];
            *(float4*)&b[4] = *(float4*)&Bs[k][tc * 8 + 4];
            #pragma unroll
            for (int i = 0; i < 8; i++)
                #pragma unroll
                for (int j = 0; j < 8; j++)
                    acc[i][j] += a[i] * b[j];
        }
        __syncthreads();
    }
    #pragma unroll
    for (int i = 0; i < 8; i++) {
        float* dst = C + (size_t)(m0 + tr * 8 + i) * NHID + tc * 8;
        float4 v0 = make_float4(acc[i][0], acc[i][1], acc[i][2], acc[i][3]);
        float4 v1 = make_float4(acc[i][4], acc[i][5], acc[i][6], acc[i][7]);
        *(float4*)dst = v0;
        *(float4*)(dst + 4) = v1;
    }
}

// ---------------- K1b: f1[h,n] = Wh[h,n,:]·a1[h], f2 likewise ----------------
__global__ void f12_kernel(const float* __restrict__ a1, const float* __restrict__ a2) {
    int gw = (blockIdx.x * blockDim.x + threadIdx.x) >> 5;
    int lane = threadIdx.x & 31;
    if (gw >= NHEADS * N_NODES) return;
    int h = gw >> 12;
    const float* wh = g_Wh + (size_t)gw * NHID;
    const float* A1 = a1 + h * NHID;
    const float* A2 = a2 + h * NHID;
    float s1 = 0.f, s2 = 0.f;
    #pragma unroll
    for (int d = lane; d < NHID; d += 32) {
        float v = wh[d];
        s1 += v * A1[d];
        s2 += v * A2[d];
    }
    #pragma unroll
    for (int o = 16; o; o >>= 1) {
        s1 += __shfl_xor_sync(~0u, s1, o);
        s2 += __shfl_xor_sync(~0u, s2, o);
    }
    if (lane == 0) { g_f1[gw] = s1; g_f2[gw] = s2; }
}

// ---------------- K2: flash GAT layer-1 ----------------
// grid (N/64, H), 256 threads. Online softmax over j, accumulate O[64][128].
__global__ __launch_bounds__(256) void gat_attn1(const int* __restrict__ adj) {
    extern __shared__ float smem[];
    float (*WhS)[NHID] = (float(*)[NHID])smem;              // 64x128
    float (*P)[64]     = (float(*)[64])(smem + 64 * NHID);  // 64x64
    float* m_s     = smem + 64 * NHID + 64 * 64;
    float* l_s     = m_s + 64;
    float* scale_s = l_s + 64;

    const int h  = blockIdx.y;
    const int i0 = blockIdx.x * 64;
    const int tid = threadIdx.x;
    const int lane = tid & 31, warp = tid >> 5;

    if (tid < 64) { m_s[tid] = -INFINITY; l_s[tid] = 0.f; }

    float f1r[8];
    #pragma unroll
    for (int rr = 0; rr < 8; rr++)
        f1r[rr] = g_f1[h * N_NODES + i0 + warp * 8 + rr];

    const int tr = tid >> 4, tc = tid & 15;   // rows {tr,tr+16,tr+32,tr+48}, cols tc*8..+7
    float O[4][8];
    #pragma unroll
    for (int a = 0; a < 4; a++)
        #pragma unroll
        for (int b = 0; b < 8; b++) O[a][b] = 0.f;

    const float* f2h = g_f2 + h * N_NODES;
    const float* WhH = g_Wh + (size_t)h * N_NODES * NHID;

    for (int j0 = 0; j0 < N_NODES; j0 += 64) {
        __syncthreads();   // previous phase-B readers done before P/WhS rewritten
        // load Wh tile [64][128]
        #pragma unroll
        for (int t = 0; t < 8; t++) {
            int idx = tid + t * 256;
            int row = idx >> 5, q = (idx & 31) * 4;
            *(float4*)&WhS[row][q] = *(const float4*)(WhH + (size_t)(j0 + row) * NHID + q);
        }
        // --- phase A: scores + online softmax for 8 rows per warp ---
        float f2a = __ldg(f2h + j0 + lane);
        float f2b = __ldg(f2h + j0 + lane + 32);
        #pragma unroll
        for (int rr = 0; rr < 8; rr++) {
            int r = warp * 8 + rr;
            size_t arow = (size_t)(i0 + r) * N_NODES + j0;
            float z1 = f1r[rr] + f2a;
            float z2 = f1r[rr] + f2b;
            float s1 = fmaxf(z1, ALPHA_LRELU * z1);
            float s2 = fmaxf(z2, ALPHA_LRELU * z2);
            s1 = (__ldg(adj + arow + lane)      > 0) ? s1 : NEG_INF_F;
            s2 = (__ldg(adj + arow + lane + 32) > 0) ? s2 : NEG_INF_F;
            float mb = fmaxf(s1, s2);
            #pragma unroll
            for (int o = 16; o; o >>= 1) mb = fmaxf(mb, __shfl_xor_sync(~0u, mb, o));
            float m_old = m_s[r];
            float m_new = fmaxf(m_old, mb);
            float p1 = __expf(s1 - m_new);
            float p2 = __expf(s2 - m_new);
            float ls = p1 + p2;
            #pragma unroll
            for (int o = 16; o; o >>= 1) ls += __shfl_xor_sync(~0u, ls, o);
            if (lane == 0) {
                float sc = __expf(m_old - m_new);   // exp(-inf - finite) = 0 first iter
                scale_s[r] = sc;
                l_s[r] = l_s[r] * sc + ls;
                m_s[r] = m_new;
            }
            P[r][lane] = p1;
            P[r][lane + 32] = p2;
        }
        __syncthreads();
        // --- phase B: O = O*scale + P @ WhS ---
        float sc0 = scale_s[tr], sc1 = scale_s[tr + 16],
              sc2 = scale_s[tr + 32], sc3 = scale_s[tr + 48];
        #pragma unroll
        for (int b = 0; b < 8; b++) {
            O[0][b] *= sc0; O[1][b] *= sc1; O[2][b] *= sc2; O[3][b] *= sc3;
        }
        #pragma unroll 4
        for (int j = 0; j < 64; j++) {
            float wv[8];
            *(float4*)&wv[0] = *(float4*)&WhS[j][tc * 8];
            *(float4*)&wv[4] = *(float4*)&WhS[j][tc * 8 + 4];
            float p0 = P[tr][j], p1 = P[tr + 16][j], p2 = P[tr + 32][j], p3 = P[tr + 48][j];
            #pragma unroll
            for (int b = 0; b < 8; b++) {
                O[0][b] += p0 * wv[b];
                O[1][b] += p1 * wv[b];
                O[2][b] += p2 * wv[b];
                O[3][b] += p3 * wv[b];
            }
        }
    }
    __syncthreads();
    // epilogue: normalize, elu, write concat layout hcat[n][h*128+d]
    #pragma unroll
    for (int a = 0; a < 4; a++) {
        int r = tr + a * 16;
        float inv = 1.f / l_s[r];
        float vals[8];
        #pragma unroll
        for (int b = 0; b < 8; b++) {
            float v = O[a][b] * inv;
            vals[b] = (v > 0.f) ? v : expm1f(v);
        }
        float* dst = g_hcat + (size_t)(i0 + r) * (NHEADS * NHID) + h * NHID + tc * 8;
        *(float4*)dst = *(float4*)&vals[0];
        *(float4*)(dst + 4) = *(float4*)&vals[4];
    }
}

// ---------------- K3: Who = hcat @ Wo  (128x64x8 tiles) ----------------
__global__ __launch_bounds__(256) void who_gemm(const float* __restrict__ Wo) {
    const int m0 = blockIdx.x * 128;
    __shared__ float As[8][128];
    __shared__ float Bs[8][64];
    const int tid = threadIdx.x;
    const int tr = tid >> 4, tc = tid & 15;
    const int arow = tid >> 1, akq = (tid & 1) * 4;

    float acc[8][4];
    #pragma unroll
    for (int i = 0; i < 8; i++)
        #pragma unroll
        for (int j = 0; j < 4; j++) acc[i][j] = 0.f;

    for (int k0 = 0; k0 < NHEADS * NHID; k0 += 8) {
        float4 av = *(const float4*)(g_hcat + (size_t)(m0 + arow) * (NHEADS * NHID) + k0 + akq);
        As[akq + 0][arow] = av.x;
        As[akq + 1][arow] = av.y;
        As[akq + 2][arow] = av.z;
        As[akq + 3][arow] = av.w;
        if (tid < 128) {
            int bk = tid >> 4, bn = (tid & 15) * 4;
            *(float4*)&Bs[bk][bn] = *(const float4*)(Wo + (size_t)(k0 + bk) * NCLASS + bn);
        }
        __syncthreads();
        #pragma unroll
        for (int k = 0; k < 8; k++) {
            float a[8], b[4];
            *(float4*)&a[0] = *(float4*)&As[k][tr * 8];
            *(float4*)&a[4] = *(float4*)&As[k][tr * 8 + 4];
            *(float4*)&b[0] = *(float4*)&Bs[k][tc * 4];
            #pragma unroll
            for (int i = 0; i < 8; i++)
                #pragma unroll
                for (int j = 0; j < 4; j++)
                    acc[i][j] += a[i] * b[j];
        }
        __syncthreads();
    }
    #pragma unroll
    for (int i = 0; i < 8; i++) {
        float4 v = make_float4(acc[i][0], acc[i][1], acc[i][2], acc[i][3]);
        *(float4*)(g_Who + (size_t)(m0 + tr * 8 + i) * NCLASS + tc * 4) = v;
    }
}

// ---------------- K3b: g1[n] = Who[n]·ao1, g2 likewise ----------------
__global__ void g12_kernel(const float* __restrict__ ao1, const float* __restrict__ ao2) {
    int gw = (blockIdx.x * blockDim.x + threadIdx.x) >> 5;
    int lane = threadIdx.x & 31;
    if (gw >= N_NODES) return;
    const float* w = g_Who + (size_t)gw * NCLASS;
    float s1 = w[lane] * ao1[lane] + w[lane + 32] * ao1[lane + 32];
    float s2 = w[lane] * ao2[lane] + w[lane + 32] * ao2[lane + 32];
    #pragma unroll
    for (int o = 16; o; o >>= 1) {
        s1 += __shfl_xor_sync(~0u, s1, o);
        s2 += __shfl_xor_sync(~0u, s2, o);
    }
    if (lane == 0) { g_g1[gw] = s1; g_g2[gw] = s2; }
}

// ---------------- K4: flash output attention (D=64, 1 head) + elu ----------------
// grid N/32, 256 threads. thread tr=tid/8 owns row tr, cols (tid&7)*8..+7
__global__ __launch_bounds__(256) void gat_attn2(const int* __restrict__ adj,
                                                 float* __restrict__ out) {
    __shared__ float VS[64][NCLASS];   // 16 KB
    __shared__ float P[32][64];        // 8 KB
    __shared__ float m_s[32], l_s[32], scale_s[32];

    const int i0 = blockIdx.x * 32;
    const int tid = threadIdx.x;
    const int lane = tid & 31, warp = tid >> 5;

    if (tid < 32) { m_s[tid] = -INFINITY; l_s[tid] = 0.f; }

    float g1r[4];
    #pragma unroll
    for (int rr = 0; rr < 4; rr++)
        g1r[rr] = g_g1[i0 + warp * 4 + rr];

    const int tr = tid >> 3, tc = tid & 7;
    float O[8];
    #pragma unroll
    for (int b = 0; b < 8; b++) O[b] = 0.f;

    for (int j0 = 0; j0 < N_NODES; j0 += 64) {
        __syncthreads();
        // load value tile Who[j0..j0+63][0..63]
        #pragma unroll
        for (int t = 0; t < 4; t++) {
            int idx = tid + t * 256;
            int row = idx >> 4, q = (idx & 15) * 4;
            *(float4*)&VS[row][q] = *(const float4*)(g_Who + (size_t)(j0 + row) * NCLASS + q);
        }
        float g2a = __ldg(g_g2 + j0 + lane);
        float g2b = __ldg(g_g2 + j0 + lane + 32);
        #pragma unroll
        for (int rr = 0; rr < 4; rr++) {
            int r = warp * 4 + rr;
            size_t arow = (size_t)(i0 + r) * N_NODES + j0;
            float z1 = g1r[rr] + g2a;
            float z2 = g1r[rr] + g2b;
            float s1 = fmaxf(z1, ALPHA_LRELU * z1);
            float s2 = fmaxf(z2, ALPHA_LRELU * z2);
            s1 = (__ldg(adj + arow + lane)      > 0) ? s1 : NEG_INF_F;
            s2 = (__ldg(adj + arow + lane + 32) > 0) ? s2 : NEG_INF_F;
            float mb = fmaxf(s1, s2);
            #pragma unroll
            for (int o = 16; o; o >>= 1) mb = fmaxf(mb, __shfl_xor_sync(~0u, mb, o));
            float m_old = m_s[r];
            float m_new = fmaxf(m_old, mb);
            float p1 = __expf(s1 - m_new);
            float p2 = __expf(s2 - m_new);
            float ls = p1 + p2;
            #pragma unroll
            for (int o = 16; o; o >>= 1) ls += __shfl_xor_sync(~0u, ls, o);
            if (lane == 0) {
                float sc = __expf(m_old - m_new);
                scale_s[r] = sc;
                l_s[r] = l_s[r] * sc + ls;
                m_s[r] = m_new;
            }
            P[r][lane] = p1;
            P[r][lane + 32] = p2;
        }
        __syncthreads();
        float sc = scale_s[tr];
        #pragma unroll
        for (int b = 0; b < 8; b++) O[b] *= sc;
        #pragma unroll 4
        for (int j = 0; j < 64; j++) {
            float wv[8];
            *(float4*)&wv[0] = *(float4*)&VS[j][tc * 8];
            *(float4*)&wv[4] = *(float4*)&VS[j][tc * 8 + 4];
            float p = P[tr][j];
            #pragma unroll
            for (int b = 0; b < 8; b++) O[b] += p * wv[b];
        }
    }
    __syncthreads();
    float inv = 1.f / l_s[tr];
    float vals[8];
    #pragma unroll
    for (int b = 0; b < 8; b++) {
        float v = O[b] * inv;
        vals[b] = (v > 0.f) ? v : expm1f(v);
    }
    float* dst = out + (size_t)(i0 + tr) * NCLASS + tc * 8;
    *(float4*)dst = *(float4*)&vals[0];
    *(float4*)(dst + 4) = *(float4*)&vals[4];
}

// ---------------- K5: log_softmax over 64 classes, in-place ----------------
__global__ void logsoftmax_kernel(float* __restrict__ out) {
    int gw = (blockIdx.x * blockDim.x + threadIdx.x) >> 5;
    int lane = threadIdx.x & 31;
    if (gw >= N_NODES) return;
    float* row = out + (size_t)gw * NCLASS;
    float v1 = row[lane], v2 = row[lane + 32];
    float m = fmaxf(v1, v2);
    #pragma unroll
    for (int o = 16; o; o >>= 1) m = fmaxf(m, __shfl_xor_sync(~0u, m, o));
    float s = __expf(v1 - m) + __expf(v2 - m);
    #pragma unroll
    for (int o = 16; o; o >>= 1) s += __shfl_xor_sync(~0u, s, o);
    float ls = m + logf(s);
    row[lane] = v1 - ls;
    row[lane + 32] = v2 - ls;
}

// ---------------- launch ----------------
extern "C" void kernel_launch(void* const* d_in, const int* in_sizes, int n_in,
                              void* d_out, int out_size) {
    const float* x   = (const float*)d_in[0];
    const int*   adj = (const int*)  d_in[1];
    const float* W   = (const float*)d_in[2];
    const float* a1  = (const float*)d_in[3];
    const float* a2  = (const float*)d_in[4];
    const float* Wo  = (const float*)d_in[5];
    const float* ao1 = (const float*)d_in[6];
    const float* ao2 = (const float*)d_in[7];
    float* out = (float*)d_out;

    const int smem1 = (64 * NHID + 64 * 64 + 3 * 64) * (int)sizeof(float);  // 49920 B
    cudaFuncSetAttribute(gat_attn1, cudaFuncAttributeMaxDynamicSharedMemorySize, smem1);

    wh_gemm<<<dim3(N_NODES / 128, NHEADS), 256>>>(x, W);
    f12_kernel<<<(NHEADS * N_NODES) / 8, 256>>>(a1, a2);
    gat_attn1<<<dim3(N_NODES / 64, NHEADS), 256, smem1>>>(adj);
    who_gemm<<<N_NODES / 128, 256>>>(Wo);
    g12_kernel<<<N_NODES / 8, 256>>>(ao1, ao2);
    gat_attn2<<<N_NODES / 32, 256>>>(adj, out);
    logsoftmax_kernel<<<N_NODES / 8, 256>>>(out);
}

// round 2
// speedup vs baseline: 1.7154x; 1.7154x over previous
#include <cuda_runtime.h>
#include <math.h>

#define N_NODES 4096
#define NFEAT   1024
#define NHID    128
#define NHEADS  8
#define NCLASS  64
#define NWORDS  (N_NODES / 32)     // 128 words per adj row
#define ALPHA_LRELU 0.2f

// ---------------- scratch (static device globals; no allocation) ----------------
__device__ float g_Wh[NHEADS * N_NODES * NHID];        // 16 MB
__device__ float g_f1[NHEADS * N_NODES];
__device__ float g_f2[NHEADS * N_NODES];
__device__ float g_f2max[NHEADS];
__device__ float g_hcat[N_NODES * NHEADS * NHID];      // 16 MB
__device__ float g_WhoP[4 * N_NODES * NCLASS];         // split-K partials, 4 MB
__device__ float g_Who[N_NODES * NCLASS];
__device__ float g_g1[N_NODES];
__device__ float g_g2[N_NODES];
__device__ float g_g2max;
__device__ unsigned g_adjbits[N_NODES * NWORDS];       // 2 MB bit mask

typedef unsigned long long ull;

__device__ __forceinline__ ull pack2(float lo, float hi) {
    ull r; asm("mov.b64 %0,{%1,%2};" : "=l"(r) : "f"(lo), "f"(hi)); return r;
}
__device__ __forceinline__ float2 unpack2(ull v) {
    float2 f; asm("mov.b64 {%0,%1},%2;" : "=f"(f.x), "=f"(f.y) : "l"(v)); return f;
}
// packed fp32 dual FMA (FFMA2) — 2x fp32 FMA throughput on sm_103a
__device__ __forceinline__ ull fma2(ull a, ull b, ull c) {
    ull d; asm("fma.rn.f32x2 %0,%1,%2,%3;" : "=l"(d) : "l"(a), "l"(b), "l"(c)); return d;
}
__device__ __forceinline__ float lrelu(float z) { return fmaxf(z, ALPHA_LRELU * z); }

// ---------------- K0: bit-pack adjacency ----------------
__global__ void bitpack_kernel(const int* __restrict__ adj) {
    int e = blockIdx.x * 256 + threadIdx.x;
    unsigned m = __ballot_sync(~0u, adj[e] > 0);
    if ((threadIdx.x & 31) == 0) g_adjbits[e >> 5] = m;
}

// ---------------- K1: Wh[h] = x @ W[h]  (128x128 tile, kt=16, f32x2) ----------------
__global__ __launch_bounds__(256) void wh_gemm(const float* __restrict__ x,
                                               const float* __restrict__ W) {
    __shared__ float As[16][128];
    __shared__ float Bs[16][128];
    const int h = blockIdx.y, m0 = blockIdx.x * 128;
    const float* B = W + (size_t)h * NFEAT * NHID;
    const int tid = threadIdx.x;
    const int tr = tid >> 4, tc = tid & 15;
    const int am = tid >> 1, ak = (tid & 1) * 8;
    const int bk = tid >> 5, bn = (tid & 31) * 4;

    ull acc[8][4];
    #pragma unroll
    for (int i = 0; i < 8; i++)
        #pragma unroll
        for (int j = 0; j < 4; j++) acc[i][j] = 0ull;

    for (int k0 = 0; k0 < NFEAT; k0 += 16) {
        float4 a0 = *(const float4*)(x + (size_t)(m0 + am) * NFEAT + k0 + ak);
        float4 a1v = *(const float4*)(x + (size_t)(m0 + am) * NFEAT + k0 + ak + 4);
        As[ak + 0][am] = a0.x; As[ak + 1][am] = a0.y;
        As[ak + 2][am] = a0.z; As[ak + 3][am] = a0.w;
        As[ak + 4][am] = a1v.x; As[ak + 5][am] = a1v.y;
        As[ak + 6][am] = a1v.z; As[ak + 7][am] = a1v.w;
        *(float4*)&Bs[bk][bn]     = *(const float4*)(B + (size_t)(k0 + bk) * NHID + bn);
        *(float4*)&Bs[bk + 8][bn] = *(const float4*)(B + (size_t)(k0 + bk + 8) * NHID + bn);
        __syncthreads();
        #pragma unroll
        for (int k = 0; k < 16; k++) {
            float a[8];
            *(float4*)&a[0] = *(float4*)&As[k][tr * 8];
            *(float4*)&a[4] = *(float4*)&As[k][tr * 8 + 4];
            ulonglong2 b01 = *(ulonglong2*)&Bs[k][tc * 8];
            ulonglong2 b23 = *(ulonglong2*)&Bs[k][tc * 8 + 4];
            #pragma unroll
            for (int i = 0; i < 8; i++) {
                ull ap = pack2(a[i], a[i]);
                acc[i][0] = fma2(ap, b01.x, acc[i][0]);
                acc[i][1] = fma2(ap, b01.y, acc[i][1]);
                acc[i][2] = fma2(ap, b23.x, acc[i][2]);
                acc[i][3] = fma2(ap, b23.y, acc[i][3]);
            }
        }
        __syncthreads();
    }
    float* C = g_Wh + (size_t)h * N_NODES * NHID;
    #pragma unroll
    for (int i = 0; i < 8; i++) {
        ulonglong2 v0; v0.x = acc[i][0]; v0.y = acc[i][1];
        ulonglong2 v1; v1.x = acc[i][2]; v1.y = acc[i][3];
        float* dst = C + (size_t)(m0 + tr * 8 + i) * NHID + tc * 8;
        *(ulonglong2*)dst = v0;
        *(ulonglong2*)(dst + 4) = v1;
    }
}

// ---------------- K1b: f1/f2 = Wh · a1/a2 ----------------
__global__ void f12_kernel(const float* __restrict__ a1, const float* __restrict__ a2) {
    int gw = (blockIdx.x * blockDim.x + threadIdx.x) >> 5;
    int lane = threadIdx.x & 31;
    if (gw >= NHEADS * N_NODES) return;
    int h = gw >> 12;
    const float* wh = g_Wh + (size_t)gw * NHID;
    const float* A1 = a1 + h * NHID;
    const float* A2 = a2 + h * NHID;
    float s1 = 0.f, s2 = 0.f;
    #pragma unroll
    for (int d = lane; d < NHID; d += 32) {
        float v = wh[d];
        s1 += v * A1[d];
        s2 += v * A2[d];
    }
    #pragma unroll
    for (int o = 16; o; o >>= 1) {
        s1 += __shfl_xor_sync(~0u, s1, o);
        s2 += __shfl_xor_sync(~0u, s2, o);
    }
    if (lane == 0) { g_f1[gw] = s1; g_f2[gw] = s2; }
}

// ---------------- K1c: per-head max of f2 ----------------
__global__ void f2max_kernel() {
    int w = threadIdx.x >> 5, lane = threadIdx.x & 31;
    const float* f2 = g_f2 + w * N_NODES;
    float m = -INFINITY;
    for (int j = lane; j < N_NODES; j += 32) m = fmaxf(m, f2[j]);
    #pragma unroll
    for (int o = 16; o; o >>= 1) m = fmaxf(m, __shfl_xor_sync(~0u, m, o));
    if (lane == 0) g_f2max[w] = m;
}

// ---------------- K2: flash GAT layer-1 (one-pass softmax, f32x2) ----------------
// grid (32, 8), 256 threads; block handles 128 rows x 128 dims of one head.
__global__ __launch_bounds__(256) void gat_attn1() {
    extern __shared__ float sm[];
    float (*WhS)[NHID] = (float(*)[NHID])sm;                 // 64 x 128
    float (*P)[65]     = (float(*)[65])(sm + 64 * NHID);     // 128 x 65 (padded)
    float* l_s = sm + 64 * NHID + 128 * 65;                  // 128

    const int h = blockIdx.y, i0 = blockIdx.x * 128;
    const int tid = threadIdx.x, lane = tid & 31, w = tid >> 5;
    const float* WhH = g_Wh + (size_t)h * N_NODES * NHID;
    const float* f2h = g_f2 + h * N_NODES;
    const float F2M = g_f2max[h];

    float f1v[16], Mv[16], lacc[16];
    #pragma unroll
    for (int rr = 0; rr < 16; rr++) {
        f1v[rr] = g_f1[h * N_NODES + i0 + w * 16 + rr];
        Mv[rr] = lrelu(f1v[rr] + F2M);     // valid upper bound: lrelu monotone
        lacc[rr] = 0.f;
    }

    const int tr = tid >> 4, tc = tid & 15;   // thread: rows tr*8..+7, cols tc*8..+7
    ull O[8][4];
    #pragma unroll
    for (int i = 0; i < 8; i++)
        #pragma unroll
        for (int j = 0; j < 4; j++) O[i][j] = 0ull;

    for (int j0 = 0; j0 < N_NODES; j0 += 64) {
        // load Wh value tile [64][128]
        #pragma unroll
        for (int t = 0; t < 8; t++) {
            int idx = tid + t * 256;
            int row = idx >> 5, q = (idx & 31) * 4;
            *(float4*)&WhS[row][q] = *(const float4*)(WhH + (size_t)(j0 + row) * NHID + q);
        }
        // phase A: scores for 16 rows per warp (one-pass, no reductions)
        float f2a = __ldg(f2h + j0 + lane);
        float f2b = __ldg(f2h + j0 + 32 + lane);
        #pragma unroll
        for (int rr = 0; rr < 16; rr++) {
            int r = w * 16 + rr;
            uint2 bw = *(const uint2*)&g_adjbits[(size_t)(i0 + r) * NWORDS + (j0 >> 5)];
            float e1 = __expf(lrelu(f1v[rr] + f2a) - Mv[rr]);
            float e2 = __expf(lrelu(f1v[rr] + f2b) - Mv[rr]);
            float p1 = ((bw.x >> lane) & 1u) ? e1 : 0.f;
            float p2 = ((bw.y >> lane) & 1u) ? e2 : 0.f;
            P[r][lane] = p1;
            P[r][lane + 32] = p2;
            lacc[rr] += p1 + p2;
        }
        __syncthreads();
        // phase B: O += P @ WhS  (f32x2)
        #pragma unroll 4
        for (int j = 0; j < 64; j++) {
            ulonglong2 w01 = *(ulonglong2*)&WhS[j][tc * 8];
            ulonglong2 w23 = *(ulonglong2*)&WhS[j][tc * 8 + 4];
            #pragma unroll
            for (int i = 0; i < 8; i++) {
                float p = P[tr * 8 + i][j];
                ull pp = pack2(p, p);
                O[i][0] = fma2(pp, w01.x, O[i][0]);
                O[i][1] = fma2(pp, w01.y, O[i][1]);
                O[i][2] = fma2(pp, w23.x, O[i][2]);
                O[i][3] = fma2(pp, w23.y, O[i][3]);
            }
        }
        __syncthreads();
    }
    // reduce row sums l (once, at the end)
    #pragma unroll
    for (int rr = 0; rr < 16; rr++) {
        float v = lacc[rr];
        #pragma unroll
        for (int o = 16; o; o >>= 1) v += __shfl_xor_sync(~0u, v, o);
        if (lane == 0) l_s[w * 16 + rr] = v;
    }
    __syncthreads();
    // epilogue: normalize, elu, write concat layout
    #pragma unroll
    for (int i = 0; i < 8; i++) {
        int r = tr * 8 + i;
        float inv = 1.f / l_s[r];
        float o[8];
        float2 u0 = unpack2(O[i][0]); o[0] = u0.x * inv; o[1] = u0.y * inv;
        float2 u1 = unpack2(O[i][1]); o[2] = u1.x * inv; o[3] = u1.y * inv;
        float2 u2 = unpack2(O[i][2]); o[4] = u2.x * inv; o[5] = u2.y * inv;
        float2 u3 = unpack2(O[i][3]); o[6] = u3.x * inv; o[7] = u3.y * inv;
        #pragma unroll
        for (int b = 0; b < 8; b++) o[b] = (o[b] > 0.f) ? o[b] : expm1f(o[b]);
        float* dst = g_hcat + (size_t)(i0 + r) * (NHEADS * NHID) + h * NHID + tc * 8;
        *(float4*)dst = *(float4*)&o[0];
        *(float4*)(dst + 4) = *(float4*)&o[4];
    }
}

// ---------------- K3: Who = hcat @ Wo  (split-K=4, f32x2) ----------------
__global__ __launch_bounds__(256) void who_gemm(const float* __restrict__ Wo) {
    __shared__ float As[16][128];
    __shared__ float Bs[16][64];
    const int m0 = blockIdx.x * 128, kb = blockIdx.y;
    const int tid = threadIdx.x;
    const int tr = tid >> 4, tc = tid & 15;
    const int am = tid >> 1, ak = (tid & 1) * 8;
    const int bk = tid >> 4, bn = (tid & 15) * 4;

    ull acc[8][2];
    #pragma unroll
    for (int i = 0; i < 8; i++) { acc[i][0] = 0ull; acc[i][1] = 0ull; }

    const int kbeg = kb * 256, kend = kbeg + 256;
    for (int k0 = kbeg; k0 < kend; k0 += 16) {
        float4 a0 = *(const float4*)(g_hcat + (size_t)(m0 + am) * (NHEADS * NHID) + k0 + ak);
        float4 a1v = *(const float4*)(g_hcat + (size_t)(m0 + am) * (NHEADS * NHID) + k0 + ak + 4);
        As[ak + 0][am] = a0.x; As[ak + 1][am] = a0.y;
        As[ak + 2][am] = a0.z; As[ak + 3][am] = a0.w;
        As[ak + 4][am] = a1v.x; As[ak + 5][am] = a1v.y;
        As[ak + 6][am] = a1v.z; As[ak + 7][am] = a1v.w;
        *(float4*)&Bs[bk][bn] = *(const float4*)(Wo + (size_t)(k0 + bk) * NCLASS + bn);
        __syncthreads();
        #pragma unroll
        for (int k = 0; k < 16; k++) {
            float a[8];
            *(float4*)&a[0] = *(float4*)&As[k][tr * 8];
            *(float4*)&a[4] = *(float4*)&As[k][tr * 8 + 4];
            ulonglong2 b = *(ulonglong2*)&Bs[k][tc * 4];
            #pragma unroll
            for (int i = 0; i < 8; i++) {
                ull ap = pack2(a[i], a[i]);
                acc[i][0] = fma2(ap, b.x, acc[i][0]);
                acc[i][1] = fma2(ap, b.y, acc[i][1]);
            }
        }
        __syncthreads();
    }
    float* C = g_WhoP + (size_t)kb * N_NODES * NCLASS;
    #pragma unroll
    for (int i = 0; i < 8; i++) {
        ulonglong2 v; v.x = acc[i][0]; v.y = acc[i][1];
        *(ulonglong2*)(C + (size_t)(m0 + tr * 8 + i) * NCLASS + tc * 4) = v;
    }
}

// ---------------- K3b: reduce split-K partials, compute g1/g2 ----------------
__global__ void g12_kernel(const float* __restrict__ ao1, const float* __restrict__ ao2) {
    int gw = (blockIdx.x * blockDim.x + threadIdx.x) >> 5;
    int lane = threadIdx.x & 31;
    if (gw >= N_NODES) return;
    size_t base = (size_t)gw * NCLASS;
    float v1 = 0.f, v2 = 0.f;
    #pragma unroll
    for (int kb = 0; kb < 4; kb++) {
        v1 += g_WhoP[(size_t)kb * N_NODES * NCLASS + base + lane];
        v2 += g_WhoP[(size_t)kb * N_NODES * NCLASS + base + lane + 32];
    }
    g_Who[base + lane] = v1;
    g_Who[base + lane + 32] = v2;
    float s1 = v1 * ao1[lane] + v2 * ao1[lane + 32];
    float s2 = v1 * ao2[lane] + v2 * ao2[lane + 32];
    #pragma unroll
    for (int o = 16; o; o >>= 1) {
        s1 += __shfl_xor_sync(~0u, s1, o);
        s2 += __shfl_xor_sync(~0u, s2, o);
    }
    if (lane == 0) { g_g1[gw] = s1; g_g2[gw] = s2; }
}

// ---------------- K3c: global max of g2 ----------------
__global__ void g2max_kernel() {
    __shared__ float s[8];
    int tid = threadIdx.x, lane = tid & 31, w = tid >> 5;
    float m = -INFINITY;
    for (int j = tid; j < N_NODES; j += 256) m = fmaxf(m, g_g2[j]);
    #pragma unroll
    for (int o = 16; o; o >>= 1) m = fmaxf(m, __shfl_xor_sync(~0u, m, o));
    if (lane == 0) s[w] = m;
    __syncthreads();
    if (tid == 0) {
        float mm = s[0];
        #pragma unroll
        for (int i = 1; i < 8; i++) mm = fmaxf(mm, s[i]);
        g_g2max = mm;
    }
}

// ---------------- K4: output attention (one-pass softmax, f32x2) + elu ----------------
// grid 128, 256 threads; block handles 32 rows x 64 classes.
__global__ __launch_bounds__(256) void gat_attn2(float* __restrict__ out) {
    __shared__ float VS[64][NCLASS];   // 16 KB
    __shared__ float P[32][65];        // padded
    __shared__ float l_s[32];

    const int i0 = blockIdx.x * 32;
    const int tid = threadIdx.x, lane = tid & 31, w = tid >> 5;
    const float G2M = g_g2max;

    float g1v[4], Mv[4], lacc[4];
    #pragma unroll
    for (int rr = 0; rr < 4; rr++) {
        g1v[rr] = g_g1[i0 + w * 4 + rr];
        Mv[rr] = lrelu(g1v[rr] + G2M);
        lacc[rr] = 0.f;
    }

    const int tr = tid >> 4, tc = tid & 15;   // thread: rows tr*2..+1, cols tc*4..+3
    ull O[2][2];
    O[0][0] = 0ull; O[0][1] = 0ull; O[1][0] = 0ull; O[1][1] = 0ull;

    for (int j0 = 0; j0 < N_NODES; j0 += 64) {
        #pragma unroll
        for (int t = 0; t < 4; t++) {
            int idx = tid + t * 256;
            int row = idx >> 4, q = (idx & 15) * 4;
            *(float4*)&VS[row][q] = *(const float4*)(g_Who + (size_t)(j0 + row) * NCLASS + q);
        }
        float g2a = __ldg(g_g2 + j0 + lane);
        float g2b = __ldg(g_g2 + j0 + 32 + lane);
        #pragma unroll
        for (int rr = 0; rr < 4; rr++) {
            int r = w * 4 + rr;
            uint2 bw = *(const uint2*)&g_adjbits[(size_t)(i0 + r) * NWORDS + (j0 >> 5)];
            float e1 = __expf(lrelu(g1v[rr] + g2a) - Mv[rr]);
            float e2 = __expf(lrelu(g1v[rr] + g2b) - Mv[rr]);
            float p1 = ((bw.x >> lane) & 1u) ? e1 : 0.f;
            float p2 = ((bw.y >> lane) & 1u) ? e2 : 0.f;
            P[r][lane] = p1;
            P[r][lane + 32] = p2;
            lacc[rr] += p1 + p2;
        }
        __syncthreads();
        #pragma unroll 4
        for (int j = 0; j < 64; j++) {
            ulonglong2 wv = *(ulonglong2*)&VS[j][tc * 4];
            float pa = P[tr * 2][j], pb = P[tr * 2 + 1][j];
            ull ppa = pack2(pa, pa), ppb = pack2(pb, pb);
            O[0][0] = fma2(ppa, wv.x, O[0][0]);
            O[0][1] = fma2(ppa, wv.y, O[0][1]);
            O[1][0] = fma2(ppb, wv.x, O[1][0]);
            O[1][1] = fma2(ppb, wv.y, O[1][1]);
        }
        __syncthreads();
    }
    #pragma unroll
    for (int rr = 0; rr < 4; rr++) {
        float v = lacc[rr];
        #pragma unroll
        for (int o = 16; o; o >>= 1) v += __shfl_xor_sync(~0u, v, o);
        if (lane == 0) l_s[w * 4 + rr] = v;
    }
    __syncthreads();
    #pragma unroll
    for (int a = 0; a < 2; a++) {
        int r = tr * 2 + a;
        float inv = 1.f / l_s[r];
        float o[4];
        float2 u0 = unpack2(O[a][0]); o[0] = u0.x * inv; o[1] = u0.y * inv;
        float2 u1 = unpack2(O[a][1]); o[2] = u1.x * inv; o[3] = u1.y * inv;
        #pragma unroll
        for (int b = 0; b < 4; b++) o[b] = (o[b] > 0.f) ? o[b] : expm1f(o[b]);
        *(float4*)(out + (size_t)(i0 + r) * NCLASS + tc * 4) = *(float4*)&o[0];
    }
}

// ---------------- K5: log_softmax over 64 classes, in-place ----------------
__global__ void logsoftmax_kernel(float* __restrict__ out) {
    int gw = (blockIdx.x * blockDim.x + threadIdx.x) >> 5;
    int lane = threadIdx.x & 31;
    if (gw >= N_NODES) return;
    float* row = out + (size_t)gw * NCLASS;
    float v1 = row[lane], v2 = row[lane + 32];
    float m = fmaxf(v1, v2);
    #pragma unroll
    for (int o = 16; o; o >>= 1) m = fmaxf(m, __shfl_xor_sync(~0u, m, o));
    float s = __expf(v1 - m) + __expf(v2 - m);
    #pragma unroll
    for (int o = 16; o; o >>= 1) s += __shfl_xor_sync(~0u, s, o);
    float ls = m + logf(s);
    row[lane] = v1 - ls;
    row[lane + 32] = v2 - ls;
}

// ---------------- launch ----------------
extern "C" void kernel_launch(void* const* d_in, const int* in_sizes, int n_in,
                              void* d_out, int out_size) {
    const float* x   = (const float*)d_in[0];
    const int*   adj = (const int*)  d_in[1];
    const float* W   = (const float*)d_in[2];
    const float* a1  = (const float*)d_in[3];
    const float* a2  = (const float*)d_in[4];
    const float* Wo  = (const float*)d_in[5];
    const float* ao1 = (const float*)d_in[6];
    const float* ao2 = (const float*)d_in[7];
    float* out = (float*)d_out;

    const int smem1 = (64 * NHID + 128 * 65 + 128) * (int)sizeof(float);  // 66560 B
    cudaFuncSetAttribute(gat_attn1, cudaFuncAttributeMaxDynamicSharedMemorySize, smem1);

    bitpack_kernel<<<(N_NODES * N_NODES) / 256, 256>>>(adj);
    wh_gemm<<<dim3(N_NODES / 128, NHEADS), 256>>>(x, W);
    f12_kernel<<<(NHEADS * N_NODES) / 8, 256>>>(a1, a2);
    f2max_kernel<<<1, 256>>>();
    gat_attn1<<<dim3(N_NODES / 128, NHEADS), 256, smem1>>>();
    who_gemm<<<dim3(N_NODES / 128, 4), 256>>>(Wo);
    g12_kernel<<<N_NODES / 8, 256>>>(ao1, ao2);
    g2max_kernel<<<1, 256>>>();
    gat_attn2<<<N_NODES / 32, 256>>>(out);
    logsoftmax_kernel<<<N_NODES / 8, 256>>>(out);
}

// round 3
// speedup vs baseline: 1.9010x; 1.1082x over previous
#include <cuda_runtime.h>
#include <math.h>

#define N_NODES 4096
#define NFEAT   1024
#define NHID    128
#define NHEADS  8
#define NCLASS  64
#define NWORDS  (N_NODES / 32)     // 128 words per adj row
#define ALPHA_LRELU 0.2f

// ---------------- scratch (static device globals; no allocation) ----------------
__device__ float g_Wh[NHEADS * N_NODES * NHID];        // 16 MB
__device__ float g_f1[NHEADS * N_NODES];
__device__ float g_f2[NHEADS * N_NODES];
__device__ float g_f2max[NHEADS];
__device__ float g_hcat[N_NODES * NHEADS * NHID];      // 16 MB
__device__ float g_WhoP[4 * N_NODES * NCLASS];         // split-K partials, 4 MB
__device__ float g_Who[N_NODES * NCLASS];
__device__ float g_g1[N_NODES];
__device__ float g_g2[N_NODES];
__device__ float g_g2max;
__device__ unsigned g_adjbits[N_NODES * NWORDS];       // 2 MB bit mask

typedef unsigned long long ull;

__device__ __forceinline__ ull pack2(float lo, float hi) {
    ull r; asm("mov.b64 %0,{%1,%2};" : "=l"(r) : "f"(lo), "f"(hi)); return r;
}
__device__ __forceinline__ float2 unpack2(ull v) {
    float2 f; asm("mov.b64 {%0,%1},%2;" : "=f"(f.x), "=f"(f.y) : "l"(v)); return f;
}
// packed fp32 dual FMA (FFMA2) — 2x fp32 FMA throughput on sm_103a
__device__ __forceinline__ ull fma2(ull a, ull b, ull c) {
    ull d; asm("fma.rn.f32x2 %0,%1,%2,%3;" : "=l"(d) : "l"(a), "l"(b), "l"(c)); return d;
}
__device__ __forceinline__ float lrelu(float z) { return fmaxf(z, ALPHA_LRELU * z); }

__device__ __forceinline__ void cp16(float* dst, const float* src) {
    unsigned sa = (unsigned)__cvta_generic_to_shared(dst);
    asm volatile("cp.async.cg.shared.global [%0], [%1], 16;" :: "r"(sa), "l"(src));
}
#define CP_COMMIT()  asm volatile("cp.async.commit_group;")
#define CP_WAIT(n)   asm volatile("cp.async.wait_group %0;" :: "n"(n))

// ---------------- K0: bit-pack adjacency ----------------
__global__ void bitpack_kernel(const int* __restrict__ adj) {
    int e = blockIdx.x * 256 + threadIdx.x;
    unsigned m = __ballot_sync(~0u, adj[e] > 0);
    if ((threadIdx.x & 31) == 0) g_adjbits[e >> 5] = m;
}

// ---------------- K1: Wh[h] = x @ W[h]  (128x128 tile, kt=16, f32x2) ----------------
__global__ __launch_bounds__(256) void wh_gemm(const float* __restrict__ x,
                                               const float* __restrict__ W) {
    __shared__ float As[16][128];
    __shared__ float Bs[16][128];
    const int h = blockIdx.y, m0 = blockIdx.x * 128;
    const float* B = W + (size_t)h * NFEAT * NHID;
    const int tid = threadIdx.x;
    const int tr = tid >> 4, tc = tid & 15;
    const int am = tid >> 1, ak = (tid & 1) * 8;
    const int bk = tid >> 5, bn = (tid & 31) * 4;

    ull acc[8][4];
    #pragma unroll
    for (int i = 0; i < 8; i++)
        #pragma unroll
        for (int j = 0; j < 4; j++) acc[i][j] = 0ull;

    for (int k0 = 0; k0 < NFEAT; k0 += 16) {
        float4 a0 = *(const float4*)(x + (size_t)(m0 + am) * NFEAT + k0 + ak);
        float4 a1v = *(const float4*)(x + (size_t)(m0 + am) * NFEAT + k0 + ak + 4);
        As[ak + 0][am] = a0.x; As[ak + 1][am] = a0.y;
        As[ak + 2][am] = a0.z; As[ak + 3][am] = a0.w;
        As[ak + 4][am] = a1v.x; As[ak + 5][am] = a1v.y;
        As[ak + 6][am] = a1v.z; As[ak + 7][am] = a1v.w;
        *(float4*)&Bs[bk][bn]     = *(const float4*)(B + (size_t)(k0 + bk) * NHID + bn);
        *(float4*)&Bs[bk + 8][bn] = *(const float4*)(B + (size_t)(k0 + bk + 8) * NHID + bn);
        __syncthreads();
        #pragma unroll
        for (int k = 0; k < 16; k++) {
            float a[8];
            *(float4*)&a[0] = *(float4*)&As[k][tr * 8];
            *(float4*)&a[4] = *(float4*)&As[k][tr * 8 + 4];
            ulonglong2 b01 = *(ulonglong2*)&Bs[k][tc * 8];
            ulonglong2 b23 = *(ulonglong2*)&Bs[k][tc * 8 + 4];
            #pragma unroll
            for (int i = 0; i < 8; i++) {
                ull ap = pack2(a[i], a[i]);
                acc[i][0] = fma2(ap, b01.x, acc[i][0]);
                acc[i][1] = fma2(ap, b01.y, acc[i][1]);
                acc[i][2] = fma2(ap, b23.x, acc[i][2]);
                acc[i][3] = fma2(ap, b23.y, acc[i][3]);
            }
        }
        __syncthreads();
    }
    float* C = g_Wh + (size_t)h * N_NODES * NHID;
    #pragma unroll
    for (int i = 0; i < 8; i++) {
        ulonglong2 v0; v0.x = acc[i][0]; v0.y = acc[i][1];
        ulonglong2 v1; v1.x = acc[i][2]; v1.y = acc[i][3];
        float* dst = C + (size_t)(m0 + tr * 8 + i) * NHID + tc * 8;
        *(ulonglong2*)dst = v0;
        *(ulonglong2*)(dst + 4) = v1;
    }
}

// ---------------- K1b: f1/f2 = Wh · a1/a2 ----------------
__global__ void f12_kernel(const float* __restrict__ a1, const float* __restrict__ a2) {
    int gw = (blockIdx.x * blockDim.x + threadIdx.x) >> 5;
    int lane = threadIdx.x & 31;
    if (gw >= NHEADS * N_NODES) return;
    int h = gw >> 12;
    const float* wh = g_Wh + (size_t)gw * NHID;
    const float* A1 = a1 + h * NHID;
    const float* A2 = a2 + h * NHID;
    float s1 = 0.f, s2 = 0.f;
    #pragma unroll
    for (int d = lane; d < NHID; d += 32) {
        float v = wh[d];
        s1 += v * A1[d];
        s2 += v * A2[d];
    }
    #pragma unroll
    for (int o = 16; o; o >>= 1) {
        s1 += __shfl_xor_sync(~0u, s1, o);
        s2 += __shfl_xor_sync(~0u, s2, o);
    }
    if (lane == 0) { g_f1[gw] = s1; g_f2[gw] = s2; }
}

// ---------------- K1c: per-head max of f2 ----------------
__global__ void f2max_kernel() {
    int w = threadIdx.x >> 5, lane = threadIdx.x & 31;
    const float* f2 = g_f2 + w * N_NODES;
    float m = -INFINITY;
    for (int j = lane; j < N_NODES; j += 32) m = fmaxf(m, f2[j]);
    #pragma unroll
    for (int o = 16; o; o >>= 1) m = fmaxf(m, __shfl_xor_sync(~0u, m, o));
    if (lane == 0) g_f2max[w] = m;
}

// ---------------- K2: flash GAT layer-1 ----------------
// grid (32, 8), 256 threads, 2 blocks/SM. Block = 128 rows x 128 dims of one head.
// Phase A: lanes own rows, loop over j -> conflict-free transposed P_T[j][r].
// Phase B: 8 rows x 8 cols per thread, row-pair packed FFMA2 (P pairs direct from smem).
// Wh value tiles double-buffered via cp.async.
#define PT_S 136
__global__ __launch_bounds__(256, 2) void gat_attn1() {
    extern __shared__ float sm[];
    float* WhS = sm;                                     // 2 x 64 x 128
    float (*PT)[PT_S] = (float(*)[PT_S])(sm + 2 * 8192); // 64 x 136
    float* l_part = sm + 2 * 8192 + 64 * PT_S;           // 2 x 128

    const int h = blockIdx.y, i0 = blockIdx.x * 128;
    const int tid = threadIdx.x, lane = tid & 31, w = tid >> 5;
    const float* WhH = g_Wh + (size_t)h * N_NODES * NHID;
    const float* f2h = g_f2 + h * N_NODES;

    // phase A role: row group (w&3), j half (w>>2)
    const int rg = w & 3, jh = w >> 2;
    const int arow = i0 + rg * 32 + lane;
    const float f1r = g_f1[h * N_NODES + arow];
    const float Mr  = lrelu(f1r + g_f2max[h]);
    float lacc = 0.f;

    // phase B role
    const int tr = tid >> 4, tc = tid & 15;
    ull acc[4][8];
    #pragma unroll
    for (int a = 0; a < 4; a++)
        #pragma unroll
        for (int k = 0; k < 8; k++) acc[a][k] = 0ull;

    // preload tile 0
    {
        const float* src = WhH;
        #pragma unroll
        for (int q = 0; q < 8; q++) {
            int idx = tid + q * 256;
            cp16(WhS + (idx >> 5) * 128 + (idx & 31) * 4,
                 src + (size_t)(idx >> 5) * NHID + (idx & 31) * 4);
        }
        CP_COMMIT();
    }

    for (int t = 0; t < 64; t++) {
        const int j0 = t * 64;
        // ---- phase A: scores, transposed store ----
        {
            unsigned word = g_adjbits[(size_t)arow * NWORDS + (j0 >> 5) + jh];
            float f2v = __ldg(f2h + j0 + jh * 32 + lane);
            #pragma unroll
            for (int jj = 0; jj < 32; jj++) {
                float f2j = __shfl_sync(~0u, f2v, jj);
                float e = __expf(lrelu(f1r + f2j) - Mr);
                float p = ((word >> jj) & 1u) ? e : 0.f;
                PT[jh * 32 + jj][rg * 32 + lane] = p;
                lacc += p;
            }
        }
        // prefetch next tile
        if (t + 1 < 64) {
            const float* src = WhH + (size_t)(t + 1) * 64 * NHID;
            float* dst = WhS + ((t + 1) & 1) * 8192;
            #pragma unroll
            for (int q = 0; q < 8; q++) {
                int idx = tid + q * 256;
                cp16(dst + (idx >> 5) * 128 + (idx & 31) * 4,
                     src + (size_t)(idx >> 5) * NHID + (idx & 31) * 4);
            }
            CP_COMMIT();
            CP_WAIT(1);
        } else {
            CP_WAIT(0);
        }
        __syncthreads();
        // ---- phase B: O += P^T-pairs x Wh ----
        const float* Wb = WhS + (t & 1) * 8192;
        #pragma unroll 2
        for (int j = 0; j < 64; j++) {
            ulonglong2 pA = *(ulonglong2*)&PT[j][tr * 8];       // {p0,p1},{p2,p3}
            ulonglong2 pB = *(ulonglong2*)&PT[j][tr * 8 + 4];   // {p4,p5},{p6,p7}
            float wv[8];
            *(float4*)&wv[0] = *(const float4*)(Wb + j * 128 + tc * 8);
            *(float4*)&wv[4] = *(const float4*)(Wb + j * 128 + tc * 8 + 4);
            #pragma unroll
            for (int k = 0; k < 8; k++) {
                ull wd = pack2(wv[k], wv[k]);
                acc[0][k] = fma2(pA.x, wd, acc[0][k]);
                acc[1][k] = fma2(pA.y, wd, acc[1][k]);
                acc[2][k] = fma2(pB.x, wd, acc[2][k]);
                acc[3][k] = fma2(pB.y, wd, acc[3][k]);
            }
        }
        __syncthreads();
    }
    // row sums
    l_part[jh * 128 + rg * 32 + lane] = lacc;
    __syncthreads();
    // epilogue: normalize + elu + write concat layout
    #pragma unroll
    for (int rp = 0; rp < 4; rp++) {
        int re = tr * 8 + rp * 2, ro = re + 1;
        float invE = 1.f / (l_part[re] + l_part[128 + re]);
        float invO = 1.f / (l_part[ro] + l_part[128 + ro]);
        float oe[8], oo[8];
        #pragma unroll
        for (int k = 0; k < 8; k++) {
            float2 u = unpack2(acc[rp][k]);
            float ve = u.x * invE, vo = u.y * invO;
            oe[k] = (ve > 0.f) ? ve : expm1f(ve);
            oo[k] = (vo > 0.f) ? vo : expm1f(vo);
        }
        float* dE = g_hcat + (size_t)(i0 + re) * (NHEADS * NHID) + h * NHID + tc * 8;
        float* dO = g_hcat + (size_t)(i0 + ro) * (NHEADS * NHID) + h * NHID + tc * 8;
        *(float4*)dE = *(float4*)&oe[0];
        *(float4*)(dE + 4) = *(float4*)&oe[4];
        *(float4*)dO = *(float4*)&oo[0];
        *(float4*)(dO + 4) = *(float4*)&oo[4];
    }
}

// ---------------- K3: Who = hcat @ Wo  (split-K=4, f32x2) ----------------
__global__ __launch_bounds__(256) void who_gemm(const float* __restrict__ Wo) {
    __shared__ float As[16][128];
    __shared__ float Bs[16][64];
    const int m0 = blockIdx.x * 128, kb = blockIdx.y;
    const int tid = threadIdx.x;
    const int tr = tid >> 4, tc = tid & 15;
    const int am = tid >> 1, ak = (tid & 1) * 8;
    const int bk = tid >> 4, bn = (tid & 15) * 4;

    ull acc[8][2];
    #pragma unroll
    for (int i = 0; i < 8; i++) { acc[i][0] = 0ull; acc[i][1] = 0ull; }

    const int kbeg = kb * 256, kend = kbeg + 256;
    for (int k0 = kbeg; k0 < kend; k0 += 16) {
        float4 a0 = *(const float4*)(g_hcat + (size_t)(m0 + am) * (NHEADS * NHID) + k0 + ak);
        float4 a1v = *(const float4*)(g_hcat + (size_t)(m0 + am) * (NHEADS * NHID) + k0 + ak + 4);
        As[ak + 0][am] = a0.x; As[ak + 1][am] = a0.y;
        As[ak + 2][am] = a0.z; As[ak + 3][am] = a0.w;
        As[ak + 4][am] = a1v.x; As[ak + 5][am] = a1v.y;
        As[ak + 6][am] = a1v.z; As[ak + 7][am] = a1v.w;
        *(float4*)&Bs[bk][bn] = *(const float4*)(Wo + (size_t)(k0 + bk) * NCLASS + bn);
        __syncthreads();
        #pragma unroll
        for (int k = 0; k < 16; k++) {
            float a[8];
            *(float4*)&a[0] = *(float4*)&As[k][tr * 8];
            *(float4*)&a[4] = *(float4*)&As[k][tr * 8 + 4];
            ulonglong2 b = *(ulonglong2*)&Bs[k][tc * 4];
            #pragma unroll
            for (int i = 0; i < 8; i++) {
                ull ap = pack2(a[i], a[i]);
                acc[i][0] = fma2(ap, b.x, acc[i][0]);
                acc[i][1] = fma2(ap, b.y, acc[i][1]);
            }
        }
        __syncthreads();
    }
    float* C = g_WhoP + (size_t)kb * N_NODES * NCLASS;
    #pragma unroll
    for (int i = 0; i < 8; i++) {
        ulonglong2 v; v.x = acc[i][0]; v.y = acc[i][1];
        *(ulonglong2*)(C + (size_t)(m0 + tr * 8 + i) * NCLASS + tc * 4) = v;
    }
}

// ---------------- K3b: reduce split-K partials, compute g1/g2 ----------------
__global__ void g12_kernel(const float* __restrict__ ao1, const float* __restrict__ ao2) {
    int gw = (blockIdx.x * blockDim.x + threadIdx.x) >> 5;
    int lane = threadIdx.x & 31;
    if (gw >= N_NODES) return;
    size_t base = (size_t)gw * NCLASS;
    float v1 = 0.f, v2 = 0.f;
    #pragma unroll
    for (int kb = 0; kb < 4; kb++) {
        v1 += g_WhoP[(size_t)kb * N_NODES * NCLASS + base + lane];
        v2 += g_WhoP[(size_t)kb * N_NODES * NCLASS + base + lane + 32];
    }
    g_Who[base + lane] = v1;
    g_Who[base + lane + 32] = v2;
    float s1 = v1 * ao1[lane] + v2 * ao1[lane + 32];
    float s2 = v1 * ao2[lane] + v2 * ao2[lane + 32];
    #pragma unroll
    for (int o = 16; o; o >>= 1) {
        s1 += __shfl_xor_sync(~0u, s1, o);
        s2 += __shfl_xor_sync(~0u, s2, o);
    }
    if (lane == 0) { g_g1[gw] = s1; g_g2[gw] = s2; }
}

// ---------------- K3c: global max of g2 ----------------
__global__ void g2max_kernel() {
    __shared__ float s[8];
    int tid = threadIdx.x, lane = tid & 31, w = tid >> 5;
    float m = -INFINITY;
    for (int j = tid; j < N_NODES; j += 256) m = fmaxf(m, g_g2[j]);
    #pragma unroll
    for (int o = 16; o; o >>= 1) m = fmaxf(m, __shfl_xor_sync(~0u, m, o));
    if (lane == 0) s[w] = m;
    __syncthreads();
    if (tid == 0) {
        float mm = s[0];
        #pragma unroll
        for (int i = 1; i < 8; i++) mm = fmaxf(mm, s[i]);
        g_g2max = mm;
    }
}

// ---------------- K4: output attention (one-pass softmax, f32x2) + elu ----------------
__global__ __launch_bounds__(256) void gat_attn2(float* __restrict__ out) {
    __shared__ float VS[64][NCLASS];   // 16 KB
    __shared__ float P[32][65];
    __shared__ float l_s[32];

    const int i0 = blockIdx.x * 32;
    const int tid = threadIdx.x, lane = tid & 31, w = tid >> 5;
    const float G2M = g_g2max;

    float g1v[4], Mv[4], lacc[4];
    #pragma unroll
    for (int rr = 0; rr < 4; rr++) {
        g1v[rr] = g_g1[i0 + w * 4 + rr];
        Mv[rr] = lrelu(g1v[rr] + G2M);
        lacc[rr] = 0.f;
    }

    const int tr = tid >> 4, tc = tid & 15;
    ull O[2][2];
    O[0][0] = 0ull; O[0][1] = 0ull; O[1][0] = 0ull; O[1][1] = 0ull;

    for (int j0 = 0; j0 < N_NODES; j0 += 64) {
        #pragma unroll
        for (int t = 0; t < 4; t++) {
            int idx = tid + t * 256;
            int row = idx >> 4, q = (idx & 15) * 4;
            *(float4*)&VS[row][q] = *(const float4*)(g_Who + (size_t)(j0 + row) * NCLASS + q);
        }
        float g2a = __ldg(g_g2 + j0 + lane);
        float g2b = __ldg(g_g2 + j0 + 32 + lane);
        #pragma unroll
        for (int rr = 0; rr < 4; rr++) {
            int r = w * 4 + rr;
            uint2 bw = *(const uint2*)&g_adjbits[(size_t)(i0 + r) * NWORDS + (j0 >> 5)];
            float e1 = __expf(lrelu(g1v[rr] + g2a) - Mv[rr]);
            float e2 = __expf(lrelu(g1v[rr] + g2b) - Mv[rr]);
            float p1 = ((bw.x >> lane) & 1u) ? e1 : 0.f;
            float p2 = ((bw.y >> lane) & 1u) ? e2 : 0.f;
            P[r][lane] = p1;
            P[r][lane + 32] = p2;
            lacc[rr] += p1 + p2;
        }
        __syncthreads();
        #pragma unroll 4
        for (int j = 0; j < 64; j++) {
            ulonglong2 wv = *(ulonglong2*)&VS[j][tc * 4];
            float pa = P[tr * 2][j], pb = P[tr * 2 + 1][j];
            ull ppa = pack2(pa, pa), ppb = pack2(pb, pb);
            O[0][0] = fma2(ppa, wv.x, O[0][0]);
            O[0][1] = fma2(ppa, wv.y, O[0][1]);
            O[1][0] = fma2(ppb, wv.x, O[1][0]);
            O[1][1] = fma2(ppb, wv.y, O[1][1]);
        }
        __syncthreads();
    }
    #pragma unroll
    for (int rr = 0; rr < 4; rr++) {
        float v = lacc[rr];
        #pragma unroll
        for (int o = 16; o; o >>= 1) v += __shfl_xor_sync(~0u, v, o);
        if (lane == 0) l_s[w * 4 + rr] = v;
    }
    __syncthreads();
    #pragma unroll
    for (int a = 0; a < 2; a++) {
        int r = tr * 2 + a;
        float inv = 1.f / l_s[r];
        float o[4];
        float2 u0 = unpack2(O[a][0]); o[0] = u0.x * inv; o[1] = u0.y * inv;
        float2 u1 = unpack2(O[a][1]); o[2] = u1.x * inv; o[3] = u1.y * inv;
        #pragma unroll
        for (int b = 0; b < 4; b++) o[b] = (o[b] > 0.f) ? o[b] : expm1f(o[b]);
        *(float4*)(out + (size_t)(i0 + r) * NCLASS + tc * 4) = *(float4*)&o[0];
    }
}

// ---------------- K5: log_softmax over 64 classes, in-place ----------------
__global__ void logsoftmax_kernel(float* __restrict__ out) {
    int gw = (blockIdx.x * blockDim.x + threadIdx.x) >> 5;
    int lane = threadIdx.x & 31;
    if (gw >= N_NODES) return;
    float* row = out + (size_t)gw * NCLASS;
    float v1 = row[lane], v2 = row[lane + 32];
    float m = fmaxf(v1, v2);
    #pragma unroll
    for (int o = 16; o; o >>= 1) m = fmaxf(m, __shfl_xor_sync(~0u, m, o));
    float s = __expf(v1 - m) + __expf(v2 - m);
    #pragma unroll
    for (int o = 16; o; o >>= 1) s += __shfl_xor_sync(~0u, s, o);
    float ls = m + logf(s);
    row[lane] = v1 - ls;
    row[lane + 32] = v2 - ls;
}

// ---------------- launch ----------------
extern "C" void kernel_launch(void* const* d_in, const int* in_sizes, int n_in,
                              void* d_out, int out_size) {
    const float* x   = (const float*)d_in[0];
    const int*   adj = (const int*)  d_in[1];
    const float* W   = (const float*)d_in[2];
    const float* a1  = (const float*)d_in[3];
    const float* a2  = (const float*)d_in[4];
    const float* Wo  = (const float*)d_in[5];
    const float* ao1 = (const float*)d_in[6];
    const float* ao2 = (const float*)d_in[7];
    float* out = (float*)d_out;

    const int smem1 = (2 * 8192 + 64 * PT_S + 2 * 128) * (int)sizeof(float);  // 101376 B
    cudaFuncSetAttribute(gat_attn1, cudaFuncAttributeMaxDynamicSharedMemorySize, smem1);

    bitpack_kernel<<<(N_NODES * N_NODES) / 256, 256>>>(adj);
    wh_gemm<<<dim3(N_NODES / 128, NHEADS), 256>>>(x, W);
    f12_kernel<<<(NHEADS * N_NODES) / 8, 256>>>(a1, a2);
    f2max_kernel<<<1, 256>>>();
    gat_attn1<<<dim3(N_NODES / 128, NHEADS), 256, smem1>>>();
    who_gemm<<<dim3(N_NODES / 128, 4), 256>>>(Wo);
    g12_kernel<<<N_NODES / 8, 256>>>(ao1, ao2);
    g2max_kernel<<<1, 256>>>();
    gat_attn2<<<N_NODES / 32, 256>>>(out);
    logsoftmax_kernel<<<N_NODES / 8, 256>>>(out);
}

// round 4
// speedup vs baseline: 1.9026x; 1.0008x over previous
#include <cuda_runtime.h>
#include <math.h>

#define N_NODES 4096
#define NFEAT   1024
#define NHID    128
#define NHEADS  8
#define NCLASS  64
#define NWORDS  (N_NODES / 32)     // 128 words per adj row
#define ALPHA_LRELU 0.2f

// ---------------- scratch (static device globals; no allocation) ----------------
__device__ float g_Wh[NHEADS * N_NODES * NHID];        // 16 MB
__device__ float g_f1[NHEADS * N_NODES];
__device__ float g_f2[NHEADS * N_NODES];
__device__ float g_f2max[NHEADS];
__device__ float g_hcat[N_NODES * NHEADS * NHID];      // 16 MB
__device__ float g_WhoP[4 * N_NODES * NCLASS];         // split-K partials, 4 MB
__device__ float g_Who[N_NODES * NCLASS];
__device__ float g_g1[N_NODES];
__device__ float g_g2[N_NODES];
__device__ float g_g2max;
__device__ unsigned g_adjbits[N_NODES * NWORDS];       // 2 MB bit mask

typedef unsigned long long ull;

__device__ __forceinline__ ull pack2(float lo, float hi) {
    ull r; asm("mov.b64 %0,{%1,%2};" : "=l"(r) : "f"(lo), "f"(hi)); return r;
}
__device__ __forceinline__ float2 unpack2(ull v) {
    float2 f; asm("mov.b64 {%0,%1},%2;" : "=f"(f.x), "=f"(f.y) : "l"(v)); return f;
}
// packed fp32 dual FMA (FFMA2) — 2x fp32 FMA throughput on sm_103a
__device__ __forceinline__ ull fma2(ull a, ull b, ull c) {
    ull d; asm("fma.rn.f32x2 %0,%1,%2,%3;" : "=l"(d) : "l"(a), "l"(b), "l"(c)); return d;
}
__device__ __forceinline__ float lrelu(float z) { return fmaxf(z, ALPHA_LRELU * z); }

__device__ __forceinline__ void cp16(float* dst, const float* src) {
    unsigned sa = (unsigned)__cvta_generic_to_shared(dst);
    asm volatile("cp.async.cg.shared.global [%0], [%1], 16;" :: "r"(sa), "l"(src));
}
#define CP_COMMIT()  asm volatile("cp.async.commit_group;")
#define CP_WAIT(n)   asm volatile("cp.async.wait_group %0;" :: "n"(n))

// ---------------- K0: bit-pack adjacency ----------------
__global__ void bitpack_kernel(const int* __restrict__ adj) {
    int e = blockIdx.x * 256 + threadIdx.x;
    unsigned m = __ballot_sync(~0u, adj[e] > 0);
    if ((threadIdx.x & 31) == 0) g_adjbits[e >> 5] = m;
}

// ---------------- K1: Wh[h] = x @ W[h]  (128x128 tile, kt=16, f32x2) ----------------
__global__ __launch_bounds__(256) void wh_gemm(const float* __restrict__ x,
                                               const float* __restrict__ W) {
    __shared__ float As[16][128];
    __shared__ float Bs[16][128];
    const int h = blockIdx.y, m0 = blockIdx.x * 128;
    const float* B = W + (size_t)h * NFEAT * NHID;
    const int tid = threadIdx.x;
    const int tr = tid >> 4, tc = tid & 15;
    const int am = tid >> 1, ak = (tid & 1) * 8;
    const int bk = tid >> 5, bn = (tid & 31) * 4;

    ull acc[8][4];
    #pragma unroll
    for (int i = 0; i < 8; i++)
        #pragma unroll
        for (int j = 0; j < 4; j++) acc[i][j] = 0ull;

    for (int k0 = 0; k0 < NFEAT; k0 += 16) {
        float4 a0 = *(const float4*)(x + (size_t)(m0 + am) * NFEAT + k0 + ak);
        float4 a1v = *(const float4*)(x + (size_t)(m0 + am) * NFEAT + k0 + ak + 4);
        As[ak + 0][am] = a0.x; As[ak + 1][am] = a0.y;
        As[ak + 2][am] = a0.z; As[ak + 3][am] = a0.w;
        As[ak + 4][am] = a1v.x; As[ak + 5][am] = a1v.y;
        As[ak + 6][am] = a1v.z; As[ak + 7][am] = a1v.w;
        *(float4*)&Bs[bk][bn]     = *(const float4*)(B + (size_t)(k0 + bk) * NHID + bn);
        *(float4*)&Bs[bk + 8][bn] = *(const float4*)(B + (size_t)(k0 + bk + 8) * NHID + bn);
        __syncthreads();
        #pragma unroll
        for (int k = 0; k < 16; k++) {
            float a[8];
            *(float4*)&a[0] = *(float4*)&As[k][tr * 8];
            *(float4*)&a[4] = *(float4*)&As[k][tr * 8 + 4];
            ulonglong2 b01 = *(ulonglong2*)&Bs[k][tc * 8];
            ulonglong2 b23 = *(ulonglong2*)&Bs[k][tc * 8 + 4];
            #pragma unroll
            for (int i = 0; i < 8; i++) {
                ull ap = pack2(a[i], a[i]);
                acc[i][0] = fma2(ap, b01.x, acc[i][0]);
                acc[i][1] = fma2(ap, b01.y, acc[i][1]);
                acc[i][2] = fma2(ap, b23.x, acc[i][2]);
                acc[i][3] = fma2(ap, b23.y, acc[i][3]);
            }
        }
        __syncthreads();
    }
    float* C = g_Wh + (size_t)h * N_NODES * NHID;
    #pragma unroll
    for (int i = 0; i < 8; i++) {
        ulonglong2 v0; v0.x = acc[i][0]; v0.y = acc[i][1];
        ulonglong2 v1; v1.x = acc[i][2]; v1.y = acc[i][3];
        float* dst = C + (size_t)(m0 + tr * 8 + i) * NHID + tc * 8;
        *(ulonglong2*)dst = v0;
        *(ulonglong2*)(dst + 4) = v1;
    }
}

// ---------------- K1b: f1/f2 = Wh · a1/a2 ----------------
__global__ void f12_kernel(const float* __restrict__ a1, const float* __restrict__ a2) {
    int gw = (blockIdx.x * blockDim.x + threadIdx.x) >> 5;
    int lane = threadIdx.x & 31;
    if (gw >= NHEADS * N_NODES) return;
    int h = gw >> 12;
    const float* wh = g_Wh + (size_t)gw * NHID;
    const float* A1 = a1 + h * NHID;
    const float* A2 = a2 + h * NHID;
    float s1 = 0.f, s2 = 0.f;
    #pragma unroll
    for (int d = lane; d < NHID; d += 32) {
        float v = wh[d];
        s1 += v * A1[d];
        s2 += v * A2[d];
    }
    #pragma unroll
    for (int o = 16; o; o >>= 1) {
        s1 += __shfl_xor_sync(~0u, s1, o);
        s2 += __shfl_xor_sync(~0u, s2, o);
    }
    if (lane == 0) { g_f1[gw] = s1; g_f2[gw] = s2; }
}

// ---------------- K1c: per-head max of f2 ----------------
__global__ void f2max_kernel() {
    int w = threadIdx.x >> 5, lane = threadIdx.x & 31;
    const float* f2 = g_f2 + w * N_NODES;
    float m = -INFINITY;
    for (int j = lane; j < N_NODES; j += 32) m = fmaxf(m, f2[j]);
    #pragma unroll
    for (int o = 16; o; o >>= 1) m = fmaxf(m, __shfl_xor_sync(~0u, m, o));
    if (lane == 0) g_f2max[w] = m;
}

// ---------------- K2: flash GAT layer-1 ----------------
// grid (32, 8), 256 threads, 2 blocks/SM. Block = 128 rows x 128 dims of one head.
// Phase A: lanes own rows, loop over j -> conflict-free transposed P_T[j][r].
// Phase B: 8 rows x 8 cols per thread, row-pair packed FFMA2 (P pairs direct from smem).
// Wh value tiles double-buffered via cp.async.
#define PT_S 136
__global__ __launch_bounds__(256, 2) void gat_attn1() {
    extern __shared__ float sm[];
    float* WhS = sm;                                     // 2 x 64 x 128
    float (*PT)[PT_S] = (float(*)[PT_S])(sm + 2 * 8192); // 64 x 136
    float* l_part = sm + 2 * 8192 + 64 * PT_S;           // 2 x 128

    const int h = blockIdx.y, i0 = blockIdx.x * 128;
    const int tid = threadIdx.x, lane = tid & 31, w = tid >> 5;
    const float* WhH = g_Wh + (size_t)h * N_NODES * NHID;
    const float* f2h = g_f2 + h * N_NODES;

    // phase A role: row group (w&3), j half (w>>2)
    const int rg = w & 3, jh = w >> 2;
    const int arow = i0 + rg * 32 + lane;
    const float f1r = g_f1[h * N_NODES + arow];
    const float Mr  = lrelu(f1r + g_f2max[h]);
    float lacc = 0.f;

    // phase B role
    const int tr = tid >> 4, tc = tid & 15;
    ull acc[4][8];
    #pragma unroll
    for (int a = 0; a < 4; a++)
        #pragma unroll
        for (int k = 0; k < 8; k++) acc[a][k] = 0ull;

    // preload tile 0
    {
        const float* src = WhH;
        #pragma unroll
        for (int q = 0; q < 8; q++) {
            int idx = tid + q * 256;
            cp16(WhS + (idx >> 5) * 128 + (idx & 31) * 4,
                 src + (size_t)(idx >> 5) * NHID + (idx & 31) * 4);
        }
        CP_COMMIT();
    }

    for (int t = 0; t < 64; t++) {
        const int j0 = t * 64;
        // ---- phase A: scores, transposed store ----
        {
            unsigned word = g_adjbits[(size_t)arow * NWORDS + (j0 >> 5) + jh];
            float f2v = __ldg(f2h + j0 + jh * 32 + lane);
            #pragma unroll
            for (int jj = 0; jj < 32; jj++) {
                float f2j = __shfl_sync(~0u, f2v, jj);
                float e = __expf(lrelu(f1r + f2j) - Mr);
                float p = ((word >> jj) & 1u) ? e : 0.f;
                PT[jh * 32 + jj][rg * 32 + lane] = p;
                lacc += p;
            }
        }
        // prefetch next tile
        if (t + 1 < 64) {
            const float* src = WhH + (size_t)(t + 1) * 64 * NHID;
            float* dst = WhS + ((t + 1) & 1) * 8192;
            #pragma unroll
            for (int q = 0; q < 8; q++) {
                int idx = tid + q * 256;
                cp16(dst + (idx >> 5) * 128 + (idx & 31) * 4,
                     src + (size_t)(idx >> 5) * NHID + (idx & 31) * 4);
            }
            CP_COMMIT();
            CP_WAIT(1);
        } else {
            CP_WAIT(0);
        }
        __syncthreads();
        // ---- phase B: O += P^T-pairs x Wh ----
        const float* Wb = WhS + (t & 1) * 8192;
        #pragma unroll 2
        for (int j = 0; j < 64; j++) {
            ulonglong2 pA = *(ulonglong2*)&PT[j][tr * 8];       // {p0,p1},{p2,p3}
            ulonglong2 pB = *(ulonglong2*)&PT[j][tr * 8 + 4];   // {p4,p5},{p6,p7}
            float wv[8];
            *(float4*)&wv[0] = *(const float4*)(Wb + j * 128 + tc * 8);
            *(float4*)&wv[4] = *(const float4*)(Wb + j * 128 + tc * 8 + 4);
            #pragma unroll
            for (int k = 0; k < 8; k++) {
                ull wd = pack2(wv[k], wv[k]);
                acc[0][k] = fma2(pA.x, wd, acc[0][k]);
                acc[1][k] = fma2(pA.y, wd, acc[1][k]);
                acc[2][k] = fma2(pB.x, wd, acc[2][k]);
                acc[3][k] = fma2(pB.y, wd, acc[3][k]);
            }
        }
        __syncthreads();
    }
    // row sums
    l_part[jh * 128 + rg * 32 + lane] = lacc;
    __syncthreads();
    // epilogue: normalize + elu + write concat layout
    #pragma unroll
    for (int rp = 0; rp < 4; rp++) {
        int re = tr * 8 + rp * 2, ro = re + 1;
        float invE = 1.f / (l_part[re] + l_part[128 + re]);
        float invO = 1.f / (l_part[ro] + l_part[128 + ro]);
        float oe[8], oo[8];
        #pragma unroll
        for (int k = 0; k < 8; k++) {
            float2 u = unpack2(acc[rp][k]);
            float ve = u.x * invE, vo = u.y * invO;
            oe[k] = (ve > 0.f) ? ve : expm1f(ve);
            oo[k] = (vo > 0.f) ? vo : expm1f(vo);
        }
        float* dE = g_hcat + (size_t)(i0 + re) * (NHEADS * NHID) + h * NHID + tc * 8;
        float* dO = g_hcat + (size_t)(i0 + ro) * (NHEADS * NHID) + h * NHID + tc * 8;
        *(float4*)dE = *(float4*)&oe[0];
        *(float4*)(dE + 4) = *(float4*)&oe[4];
        *(float4*)dO = *(float4*)&oo[0];
        *(float4*)(dO + 4) = *(float4*)&oo[4];
    }
}

// ---------------- K3: Who = hcat @ Wo  (split-K=4, f32x2) ----------------
__global__ __launch_bounds__(256) void who_gemm(const float* __restrict__ Wo) {
    __shared__ float As[16][128];
    __shared__ float Bs[16][64];
    const int m0 = blockIdx.x * 128, kb = blockIdx.y;
    const int tid = threadIdx.x;
    const int tr = tid >> 4, tc = tid & 15;
    const int am = tid >> 1, ak = (tid & 1) * 8;
    const int bk = tid >> 4, bn = (tid & 15) * 4;

    ull acc[8][2];
    #pragma unroll
    for (int i = 0; i < 8; i++) { acc[i][0] = 0ull; acc[i][1] = 0ull; }

    const int kbeg = kb * 256, kend = kbeg + 256;
    for (int k0 = kbeg; k0 < kend; k0 += 16) {
        float4 a0 = *(const float4*)(g_hcat + (size_t)(m0 + am) * (NHEADS * NHID) + k0 + ak);
        float4 a1v = *(const float4*)(g_hcat + (size_t)(m0 + am) * (NHEADS * NHID) + k0 + ak + 4);
        As[ak + 0][am] = a0.x; As[ak + 1][am] = a0.y;
        As[ak + 2][am] = a0.z; As[ak + 3][am] = a0.w;
        As[ak + 4][am] = a1v.x; As[ak + 5][am] = a1v.y;
        As[ak + 6][am] = a1v.z; As[ak + 7][am] = a1v.w;
        *(float4*)&Bs[bk][bn] = *(const float4*)(Wo + (size_t)(k0 + bk) * NCLASS + bn);
        __syncthreads();
        #pragma unroll
        for (int k = 0; k < 16; k++) {
            float a[8];
            *(float4*)&a[0] = *(float4*)&As[k][tr * 8];
            *(float4*)&a[4] = *(float4*)&As[k][tr * 8 + 4];
            ulonglong2 b = *(ulonglong2*)&Bs[k][tc * 4];
            #pragma unroll
            for (int i = 0; i < 8; i++) {
                ull ap = pack2(a[i], a[i]);
                acc[i][0] = fma2(ap, b.x, acc[i][0]);
                acc[i][1] = fma2(ap, b.y, acc[i][1]);
            }
        }
        __syncthreads();
    }
    float* C = g_WhoP + (size_t)kb * N_NODES * NCLASS;
    #pragma unroll
    for (int i = 0; i < 8; i++) {
        ulonglong2 v; v.x = acc[i][0]; v.y = acc[i][1];
        *(ulonglong2*)(C + (size_t)(m0 + tr * 8 + i) * NCLASS + tc * 4) = v;
    }
}

// ---------------- K3b: reduce split-K partials, compute g1/g2 ----------------
__global__ void g12_kernel(const float* __restrict__ ao1, const float* __restrict__ ao2) {
    int gw = (blockIdx.x * blockDim.x + threadIdx.x) >> 5;
    int lane = threadIdx.x & 31;
    if (gw >= N_NODES) return;
    size_t base = (size_t)gw * NCLASS;
    float v1 = 0.f, v2 = 0.f;
    #pragma unroll
    for (int kb = 0; kb < 4; kb++) {
        v1 += g_WhoP[(size_t)kb * N_NODES * NCLASS + base + lane];
        v2 += g_WhoP[(size_t)kb * N_NODES * NCLASS + base + lane + 32];
    }
    g_Who[base + lane] = v1;
    g_Who[base + lane + 32] = v2;
    float s1 = v1 * ao1[lane] + v2 * ao1[lane + 32];
    float s2 = v1 * ao2[lane] + v2 * ao2[lane + 32];
    #pragma unroll
    for (int o = 16; o; o >>= 1) {
        s1 += __shfl_xor_sync(~0u, s1, o);
        s2 += __shfl_xor_sync(~0u, s2, o);
    }
    if (lane == 0) { g_g1[gw] = s1; g_g2[gw] = s2; }
}

// ---------------- K3c: global max of g2 ----------------
__global__ void g2max_kernel() {
    __shared__ float s[8];
    int tid = threadIdx.x, lane = tid & 31, w = tid >> 5;
    float m = -INFINITY;
    for (int j = tid; j < N_NODES; j += 256) m = fmaxf(m, g_g2[j]);
    #pragma unroll
    for (int o = 16; o; o >>= 1) m = fmaxf(m, __shfl_xor_sync(~0u, m, o));
    if (lane == 0) s[w] = m;
    __syncthreads();
    if (tid == 0) {
        float mm = s[0];
        #pragma unroll
        for (int i = 1; i < 8; i++) mm = fmaxf(mm, s[i]);
        g_g2max = mm;
    }
}

// ---------------- K4: output attention (one-pass softmax, f32x2) + elu ----------------
__global__ __launch_bounds__(256) void gat_attn2(float* __restrict__ out) {
    __shared__ float VS[64][NCLASS];   // 16 KB
    __shared__ float P[32][65];
    __shared__ float l_s[32];

    const int i0 = blockIdx.x * 32;
    const int tid = threadIdx.x, lane = tid & 31, w = tid >> 5;
    const float G2M = g_g2max;

    float g1v[4], Mv[4], lacc[4];
    #pragma unroll
    for (int rr = 0; rr < 4; rr++) {
        g1v[rr] = g_g1[i0 + w * 4 + rr];
        Mv[rr] = lrelu(g1v[rr] + G2M);
        lacc[rr] = 0.f;
    }

    const int tr = tid >> 4, tc = tid & 15;
    ull O[2][2];
    O[0][0] = 0ull; O[0][1] = 0ull; O[1][0] = 0ull; O[1][1] = 0ull;

    for (int j0 = 0; j0 < N_NODES; j0 += 64) {
        #pragma unroll
        for (int t = 0; t < 4; t++) {
            int idx = tid + t * 256;
            int row = idx >> 4, q = (idx & 15) * 4;
            *(float4*)&VS[row][q] = *(const float4*)(g_Who + (size_t)(j0 + row) * NCLASS + q);
        }
        float g2a = __ldg(g_g2 + j0 + lane);
        float g2b = __ldg(g_g2 + j0 + 32 + lane);
        #pragma unroll
        for (int rr = 0; rr < 4; rr++) {
            int r = w * 4 + rr;
            uint2 bw = *(const uint2*)&g_adjbits[(size_t)(i0 + r) * NWORDS + (j0 >> 5)];
            float e1 = __expf(lrelu(g1v[rr] + g2a) - Mv[rr]);
            float e2 = __expf(lrelu(g1v[rr] + g2b) - Mv[rr]);
            float p1 = ((bw.x >> lane) & 1u) ? e1 : 0.f;
            float p2 = ((bw.y >> lane) & 1u) ? e2 : 0.f;
            P[r][lane] = p1;
            P[r][lane + 32] = p2;
            lacc[rr] += p1 + p2;
        }
        __syncthreads();
        #pragma unroll 4
        for (int j = 0; j < 64; j++) {
            ulonglong2 wv = *(ulonglong2*)&VS[j][tc * 4];
            float pa = P[tr * 2][j], pb = P[tr * 2 + 1][j];
            ull ppa = pack2(pa, pa), ppb = pack2(pb, pb);
            O[0][0] = fma2(ppa, wv.x, O[0][0]);
            O[0][1] = fma2(ppa, wv.y, O[0][1]);
            O[1][0] = fma2(ppb, wv.x, O[1][0]);
            O[1][1] = fma2(ppb, wv.y, O[1][1]);
        }
        __syncthreads();
    }
    #pragma unroll
    for (int rr = 0; rr < 4; rr++) {
        float v = lacc[rr];
        #pragma unroll
        for (int o = 16; o; o >>= 1) v += __shfl_xor_sync(~0u, v, o);
        if (lane == 0) l_s[w * 4 + rr] = v;
    }
    __syncthreads();
    #pragma unroll
    for (int a = 0; a < 2; a++) {
        int r = tr * 2 + a;
        float inv = 1.f / l_s[r];
        float o[4];
        float2 u0 = unpack2(O[a][0]); o[0] = u0.x * inv; o[1] = u0.y * inv;
        float2 u1 = unpack2(O[a][1]); o[2] = u1.x * inv; o[3] = u1.y * inv;
        #pragma unroll
        for (int b = 0; b < 4; b++) o[b] = (o[b] > 0.f) ? o[b] : expm1f(o[b]);
        *(float4*)(out + (size_t)(i0 + r) * NCLASS + tc * 4) = *(float4*)&o[0];
    }
}

// ---------------- K5: log_softmax over 64 classes, in-place ----------------
__global__ void logsoftmax_kernel(float* __restrict__ out) {
    int gw = (blockIdx.x * blockDim.x + threadIdx.x) >> 5;
    int lane = threadIdx.x & 31;
    if (gw >= N_NODES) return;
    float* row = out + (size_t)gw * NCLASS;
    float v1 = row[lane], v2 = row[lane + 32];
    float m = fmaxf(v1, v2);
    #pragma unroll
    for (int o = 16; o; o >>= 1) m = fmaxf(m, __shfl_xor_sync(~0u, m, o));
    float s = __expf(v1 - m) + __expf(v2 - m);
    #pragma unroll
    for (int o = 16; o; o >>= 1) s += __shfl_xor_sync(~0u, s, o);
    float ls = m + logf(s);
    row[lane] = v1 - ls;
    row[lane + 32] = v2 - ls;
}

// ---------------- launch ----------------
extern "C" void kernel_launch(void* const* d_in, const int* in_sizes, int n_in,
                              void* d_out, int out_size) {
    const float* x   = (const float*)d_in[0];
    const int*   adj = (const int*)  d_in[1];
    const float* W   = (const float*)d_in[2];
    const float* a1  = (const float*)d_in[3];
    const float* a2  = (const float*)d_in[4];
    const float* Wo  = (const float*)d_in[5];
    const float* ao1 = (const float*)d_in[6];
    const float* ao2 = (const float*)d_in[7];
    float* out = (float*)d_out;

    const int smem1 = (2 * 8192 + 64 * PT_S + 2 * 128) * (int)sizeof(float);  // 101376 B
    cudaFuncSetAttribute(gat_attn1, cudaFuncAttributeMaxDynamicSharedMemorySize, smem1);

    bitpack_kernel<<<(N_NODES * N_NODES) / 256, 256>>>(adj);
    wh_gemm<<<dim3(N_NODES / 128, NHEADS), 256>>>(x, W);
    f12_kernel<<<(NHEADS * N_NODES) / 8, 256>>>(a1, a2);
    f2max_kernel<<<1, 256>>>();
    gat_attn1<<<dim3(N_NODES / 128, NHEADS), 256, smem1>>>();
    who_gemm<<<dim3(N_NODES / 128, 4), 256>>>(Wo);
    g12_kernel<<<N_NODES / 8, 256>>>(ao1, ao2);
    g2max_kernel<<<1, 256>>>();
    gat_attn2<<<N_NODES / 32, 256>>>(out);
    logsoftmax_kernel<<<N_NODES / 8, 256>>>(out);
}

// round 6
// speedup vs baseline: 2.6874x; 1.4125x over previous
#include <cuda_runtime.h>
#include <cuda_bf16.h>
#include <math.h>

#define N_NODES 4096
#define NFEAT   1024
#define NHID    128
#define NHEADS  8
#define NCLASS  64
#define NWORDS  (N_NODES / 32)
#define ALPHA_LRELU 0.2f

__device__ float g_Wh[NHEADS * N_NODES * NHID];
__device__ __nv_bfloat16 g_WhT_hi[NHEADS * NHID * N_NODES];
__device__ __nv_bfloat16 g_WhT_lo[NHEADS * NHID * N_NODES];
__device__ float g_f1[NHEADS * N_NODES];
__device__ float g_f2[NHEADS * N_NODES];
__device__ float2 g_e1[NHEADS * N_NODES];   // {exp(f1), exp(0.2 f1)}
__device__ float2 g_e2[NHEADS * N_NODES];   // {exp(f2), exp(0.2 f2)}
__device__ float g_hcat[N_NODES * NHEADS * NHID];
__device__ float g_WhoP[4 * N_NODES * NCLASS];
__device__ float g_Who[N_NODES * NCLASS];
__device__ float g_g1[N_NODES];
__device__ float2 g_eo1[N_NODES];
__device__ float2 g_eo2[N_NODES];
__device__ unsigned g_adjbits[N_NODES * NWORDS];

typedef unsigned long long ull;

__device__ __forceinline__ ull pack2(float lo, float hi) {
    ull r; asm("mov.b64 %0,{%1,%2};" : "=l"(r) : "f"(lo), "f"(hi)); return r;
}
__device__ __forceinline__ float2 unpack2(ull v) {
    float2 f; asm("mov.b64 {%0,%1},%2;" : "=f"(f.x), "=f"(f.y) : "l"(v)); return f;
}
__device__ __forceinline__ ull fma2(ull a, ull b, ull c) {
    ull d; asm("fma.rn.f32x2 %0,%1,%2,%3;" : "=l"(d) : "l"(a), "l"(b), "l"(c)); return d;
}
__device__ __forceinline__ void cp16(void* dst, const void* src) {
    unsigned sa = (unsigned)__cvta_generic_to_shared(dst);
    asm volatile("cp.async.cg.shared.global [%0], [%1], 16;" :: "r"(sa), "l"(src));
}
#define CP_COMMIT() asm volatile("cp.async.commit_group;")
#define CP_WAIT0()  asm volatile("cp.async.wait_group 0;")
#define CP_WAIT1()  asm volatile("cp.async.wait_group 1;")

__device__ __forceinline__ void ldsm4(unsigned* r, unsigned a) {
    asm volatile("ldmatrix.sync.aligned.m8n8.x4.shared.b16 {%0,%1,%2,%3}, [%4];"
                 : "=r"(r[0]), "=r"(r[1]), "=r"(r[2]), "=r"(r[3]) : "r"(a));
}
__device__ __forceinline__ void ldsm2(unsigned* r, unsigned a) {
    asm volatile("ldmatrix.sync.aligned.m8n8.x2.shared.b16 {%0,%1}, [%2];"
                 : "=r"(r[0]), "=r"(r[1]) : "r"(a));
}
__device__ __forceinline__ void mma16816(float* d, const unsigned* a, const unsigned* b) {
    asm volatile("mma.sync.aligned.m16n8k16.row.col.f32.bf16.bf16.f32 "
                 "{%0,%1,%2,%3}, {%4,%5,%6,%7}, {%8,%9}, {%0,%1,%2,%3};"
                 : "+f"(d[0]), "+f"(d[1]), "+f"(d[2]), "+f"(d[3])
                 : "r"(a[0]), "r"(a[1]), "r"(a[2]), "r"(a[3]), "r"(b[0]), "r"(b[1]));
}

// K0: bit-pack adjacency
__global__ void bitpack_kernel(const int* __restrict__ adj) {
    int e = blockIdx.x * 256 + threadIdx.x;
    unsigned m = __ballot_sync(~0u, adj[e] > 0);
    if ((threadIdx.x & 31) == 0) g_adjbits[e >> 5] = m;
}

// K1: Wh = x @ W  + bf16 hi/lo transposed output (WhT[d][n])
__global__ __launch_bounds__(256) void wh_gemm(const float* __restrict__ x,
                                               const float* __restrict__ W) {
    __shared__ __align__(16) char buf[33024];
    float (*As)[128] = (float(*)[128])buf;
    float (*Bs)[128] = (float(*)[128])(buf + 8192);
    const int h = blockIdx.y, m0 = blockIdx.x * 128;
    const float* B = W + (size_t)h * NFEAT * NHID;
    const int tid = threadIdx.x;
    const int tr = tid >> 4, tc = tid & 15;
    const int am = tid >> 1, ak = (tid & 1) * 8;
    const int bk = tid >> 5, bn = (tid & 31) * 4;

    ull acc[8][4];
    #pragma unroll
    for (int i = 0; i < 8; i++)
        #pragma unroll
        for (int j = 0; j < 4; j++) acc[i][j] = 0ull;

    for (int k0 = 0; k0 < NFEAT; k0 += 16) {
        float4 a0 = *(const float4*)(x + (size_t)(m0 + am) * NFEAT + k0 + ak);
        float4 a1v = *(const float4*)(x + (size_t)(m0 + am) * NFEAT + k0 + ak + 4);
        As[ak + 0][am] = a0.x; As[ak + 1][am] = a0.y;
        As[ak + 2][am] = a0.z; As[ak + 3][am] = a0.w;
        As[ak + 4][am] = a1v.x; As[ak + 5][am] = a1v.y;
        As[ak + 6][am] = a1v.z; As[ak + 7][am] = a1v.w;
        *(float4*)&Bs[bk][bn]     = *(const float4*)(B + (size_t)(k0 + bk) * NHID + bn);
        *(float4*)&Bs[bk + 8][bn] = *(const float4*)(B + (size_t)(k0 + bk + 8) * NHID + bn);
        __syncthreads();
        #pragma unroll
        for (int k = 0; k < 16; k++) {
            float a[8];
            *(float4*)&a[0] = *(float4*)&As[k][tr * 8];
            *(float4*)&a[4] = *(float4*)&As[k][tr * 8 + 4];
            ulonglong2 b01 = *(ulonglong2*)&Bs[k][tc * 8];
            ulonglong2 b23 = *(ulonglong2*)&Bs[k][tc * 8 + 4];
            #pragma unroll
            for (int i = 0; i < 8; i++) {
                ull ap = pack2(a[i], a[i]);
                acc[i][0] = fma2(ap, b01.x, acc[i][0]);
                acc[i][1] = fma2(ap, b01.y, acc[i][1]);
                acc[i][2] = fma2(ap, b23.x, acc[i][2]);
                acc[i][3] = fma2(ap, b23.y, acc[i][3]);
            }
        }
        __syncthreads();
    }
    float* C = g_Wh + (size_t)h * N_NODES * NHID;
    #pragma unroll
    for (int i = 0; i < 8; i++) {
        ulonglong2 v0; v0.x = acc[i][0]; v0.y = acc[i][1];
        ulonglong2 v1; v1.x = acc[i][2]; v1.y = acc[i][3];
        float* dst = C + (size_t)(m0 + tr * 8 + i) * NHID + tc * 8;
        *(ulonglong2*)dst = v0;
        *(ulonglong2*)(dst + 4) = v1;
    }
    __nv_bfloat16 (*smH)[129] = (__nv_bfloat16(*)[129])buf;
    __nv_bfloat16 (*smL)[129] = (__nv_bfloat16(*)[129])(buf + 16512);
    #pragma unroll 1
    for (int half = 0; half < 2; half++) {
        __syncthreads();
        if ((tc >> 3) == half) {
            #pragma unroll
            for (int i = 0; i < 8; i++)
                #pragma unroll
                for (int cc = 0; cc < 8; cc++) {
                    float2 u = unpack2(acc[i][cc >> 1]);
                    float v = (cc & 1) ? u.y : u.x;
                    __nv_bfloat16 hb = __float2bfloat16(v);
                    __nv_bfloat16 lb = __float2bfloat16(v - __bfloat162float(hb));
                    int cloc = (tc & 7) * 8 + cc;
                    smH[cloc][tr * 8 + i] = hb;
                    smL[cloc][tr * 8 + i] = lb;
                }
        }
        __syncthreads();
        int c = tid >> 2, seg = tid & 3;
        size_t base = ((size_t)h * NHID + half * 64 + c) * N_NODES + m0 + seg * 32;
        #pragma unroll
        for (int k = 0; k < 32; k++) {
            g_WhT_hi[base + k] = smH[c][seg * 32 + k];
            g_WhT_lo[base + k] = smL[c][seg * 32 + k];
        }
    }
}

// K1b: f1/f2 + factored exps
__global__ void f12_kernel(const float* __restrict__ a1, const float* __restrict__ a2) {
    int gw = (blockIdx.x * blockDim.x + threadIdx.x) >> 5;
    int lane = threadIdx.x & 31;
    if (gw >= NHEADS * N_NODES) return;
    int h = gw >> 12;
    const float* wh = g_Wh + (size_t)gw * NHID;
    const float* A1 = a1 + h * NHID;
    const float* A2 = a2 + h * NHID;
    float s1 = 0.f, s2 = 0.f;
    #pragma unroll
    for (int d = lane; d < NHID; d += 32) {
        float v = wh[d];
        s1 += v * A1[d]; s2 += v * A2[d];
    }
    #pragma unroll
    for (int o = 16; o; o >>= 1) {
        s1 += __shfl_xor_sync(~0u, s1, o);
        s2 += __shfl_xor_sync(~0u, s2, o);
    }
    if (lane == 0) {
        g_f1[gw] = s1; g_f2[gw] = s2;
        g_e1[gw] = make_float2(__expf(s1), __expf(ALPHA_LRELU * s1));
        g_e2[gw] = make_float2(__expf(s2), __expf(ALPHA_LRELU * s2));
    }
}

// K2: attn layer-1 — phase A exp-free, phase B mma.sync bf16 3-term
#define PSTRIDE 144                         // bytes per P/W smem row (72 bf16)
#define OFF_WS  0                           // 2 stages x (hi 18432 + lo 18432)
#define OFF_PHI 73728
#define OFF_PLO 92160
#define OFF_LP  110592
#define SMEM_ATTN1 111616

__global__ __launch_bounds__(256) void gat_attn1() {
    extern __shared__ __align__(16) char smx[];
    const unsigned sb = (unsigned)__cvta_generic_to_shared(smx);
    const int tid = threadIdx.x, lane = tid & 31, w = tid >> 5;
    const int h = blockIdx.y, i0 = blockIdx.x * 128;
    const int hN = h * N_NODES;

    // phase A role
    const int rg = w & 3, jh = w >> 2;
    const int r = rg * 32 + lane, arow = i0 + r;
    const float f1r = g_f1[hN + arow];
    const float2 e1 = g_e1[hN + arow];
    float lacc = 0.f;

    // phase B role
    const int mB = (w & 3) * 32, nB = (w >> 2) * 64;
    float acc[2][8][4];
    #pragma unroll
    for (int mi = 0; mi < 2; mi++)
        #pragma unroll
        for (int nt = 0; nt < 8; nt++)
            #pragma unroll
            for (int e = 0; e < 4; e++) acc[mi][nt][e] = 0.f;

    const __nv_bfloat16* WTh = g_WhT_hi + (size_t)h * NHID * N_NODES;
    const __nv_bfloat16* WTl = g_WhT_lo + (size_t)h * NHID * N_NODES;

    // prefetch W tile 0
    #pragma unroll
    for (int q = 0; q < 4; q++) {
        int idx = tid + q * 256;
        int d = idx >> 3, ch = idx & 7;
        cp16(smx + OFF_WS + d * PSTRIDE + ch * 16, WTh + (size_t)d * N_NODES + ch * 8);
        cp16(smx + OFF_WS + 18432 + d * PSTRIDE + ch * 16, WTl + (size_t)d * N_NODES + ch * 8);
    }
    CP_COMMIT();

    for (int t = 0; t < 64; t++) {
        const int s = t & 1;
        // ---- phase A: P tile (exp-free product form) ----
        {
            unsigned word = g_adjbits[(size_t)arow * NWORDS + t * 2 + jh];
            float f2v = g_f2[hN + t * 64 + jh * 32 + lane];
            float2 e2v = g_e2[hN + t * 64 + jh * 32 + lane];
            unsigned pbase = r * PSTRIDE + (jh * 32) * 2;
            #pragma unroll
            for (int jq = 0; jq < 8; jq++) {
                unsigned hv[2], lv[2];
                #pragma unroll
                for (int u = 0; u < 2; u++) {
                    float p[2];
                    #pragma unroll
                    for (int v = 0; v < 2; v++) {
                        int j = jq * 4 + u * 2 + v;
                        float f2j = __shfl_sync(~0u, f2v, j);
                        float ep  = __shfl_sync(~0u, e2v.x, j);
                        float en  = __shfl_sync(~0u, e2v.y, j);
                        float pv = (f1r + f2j > 0.f) ? e1.x * ep : e1.y * en;
                        pv = ((word >> j) & 1u) ? pv : 0.f;
                        lacc += pv;
                        p[v] = pv;
                    }
                    __nv_bfloat16 h0 = __float2bfloat16(p[0]);
                    __nv_bfloat16 h1 = __float2bfloat16(p[1]);
                    __nv_bfloat16 g0 = __float2bfloat16(p[0] - __bfloat162float(h0));
                    __nv_bfloat16 g1 = __float2bfloat16(p[1] - __bfloat162float(h1));
                    hv[u] = (unsigned)__bfloat16_as_ushort(h0) | ((unsigned)__bfloat16_as_ushort(h1) << 16);
                    lv[u] = (unsigned)__bfloat16_as_ushort(g0) | ((unsigned)__bfloat16_as_ushort(g1) << 16);
                }
                ull hp; asm("mov.b64 %0,{%1,%2};" : "=l"(hp) : "r"(hv[0]), "r"(hv[1]));
                ull lp; asm("mov.b64 %0,{%1,%2};" : "=l"(lp) : "r"(lv[0]), "r"(lv[1]));
                *(ull*)(smx + OFF_PHI + pbase + jq * 8) = hp;
                *(ull*)(smx + OFF_PLO + pbase + jq * 8) = lp;
            }
        }
        // prefetch next W tile
        if (t + 1 < 64) {
            char* dst = smx + OFF_WS + ((t + 1) & 1) * 36864;
            size_t so = (size_t)(t + 1) * 64;
            #pragma unroll
            for (int q = 0; q < 4; q++) {
                int idx = tid + q * 256;
                int d = idx >> 3, ch = idx & 7;
                cp16(dst + d * PSTRIDE + ch * 16, WTh + (size_t)d * N_NODES + so + ch * 8);
                cp16(dst + 18432 + d * PSTRIDE + ch * 16, WTl + (size_t)d * N_NODES + so + ch * 8);
            }
            CP_COMMIT();
            CP_WAIT1();
        } else {
            CP_WAIT0();
        }
        __syncthreads();
        // ---- phase B: mma.sync ----
        {
            const unsigned WH = sb + OFF_WS + s * 36864;
            const unsigned WL = WH + 18432;
            const int l4 = lane & 15;
            #pragma unroll
            for (int kt = 0; kt < 4; kt++) {
                const unsigned koff = (kt * 16 + ((lane >> 4) * 8)) * 2;
                const unsigned koffB = (kt * 16 + ((l4 >> 3) * 8)) * 2;
                unsigned ah[2][4], al[2][4];
                #pragma unroll
                for (int mi = 0; mi < 2; mi++) {
                    unsigned ao = (mB + mi * 16 + (lane & 15)) * PSTRIDE + koff;
                    ldsm4(ah[mi], sb + OFF_PHI + ao);
                    ldsm4(al[mi], sb + OFF_PLO + ao);
                }
                unsigned bh[8][2], bl[8][2];
                #pragma unroll
                for (int nt = 0; nt < 8; nt++) {
                    unsigned bo = (nB + nt * 8 + (l4 & 7)) * PSTRIDE + koffB;
                    ldsm2(bh[nt], WH + bo);
                    ldsm2(bl[nt], WL + bo);
                }
                #pragma unroll
                for (int mi = 0; mi < 2; mi++)
                    #pragma unroll
                    for (int nt = 0; nt < 8; nt++) {
                        mma16816(acc[mi][nt], ah[mi], bh[nt]);
                        mma16816(acc[mi][nt], ah[mi], bl[nt]);
                        mma16816(acc[mi][nt], al[mi], bh[nt]);
                    }
            }
        }
        __syncthreads();
    }
    ((float*)(smx + OFF_LP))[jh * 128 + r] = lacc;
    __syncthreads();
    // epilogue: normalize + elu + store
    {
        const float* LP = (const float*)(smx + OFF_LP);
        #pragma unroll
        for (int mi = 0; mi < 2; mi++)
            #pragma unroll
            for (int eh = 0; eh < 2; eh++) {
                int row = mB + mi * 16 + (lane >> 2) + eh * 8;
                float inv = 1.f / (LP[row] + LP[128 + row]);
                float* dst = g_hcat + (size_t)(i0 + row) * (NHEADS * NHID) + h * NHID + nB + (lane & 3) * 2;
                #pragma unroll
                for (int nt = 0; nt < 8; nt++) {
                    float v0 = acc[mi][nt][eh * 2] * inv;
                    float v1 = acc[mi][nt][eh * 2 + 1] * inv;
                    v0 = (v0 > 0.f) ? v0 : expm1f(v0);
                    v1 = (v1 > 0.f) ? v1 : expm1f(v1);
                    *(float2*)(dst + nt * 8) = make_float2(v0, v1);
                }
            }
    }
}

// K3: Who = hcat @ Wo (split-K=4)
__global__ __launch_bounds__(256) void who_gemm(const float* __restrict__ Wo) {
    __shared__ float As[16][128];
    __shared__ float Bs[16][64];
    const int m0 = blockIdx.x * 128, kb = blockIdx.y;
    const int tid = threadIdx.x;
    const int tr = tid >> 4, tc = tid & 15;
    const int am = tid >> 1, ak = (tid & 1) * 8;
    const int bk = tid >> 4, bn = (tid & 15) * 4;

    ull acc[8][2];
    #pragma unroll
    for (int i = 0; i < 8; i++) { acc[i][0] = 0ull; acc[i][1] = 0ull; }
    const int kbeg = kb * 256, kend = kbeg + 256;
    for (int k0 = kbeg; k0 < kend; k0 += 16) {
        float4 a0 = *(const float4*)(g_hcat + (size_t)(m0 + am) * (NHEADS * NHID) + k0 + ak);
        float4 a1v = *(const float4*)(g_hcat + (size_t)(m0 + am) * (NHEADS * NHID) + k0 + ak + 4);
        As[ak + 0][am] = a0.x; As[ak + 1][am] = a0.y;
        As[ak + 2][am] = a0.z; As[ak + 3][am] = a0.w;
        As[ak + 4][am] = a1v.x; As[ak + 5][am] = a1v.y;
        As[ak + 6][am] = a1v.z; As[ak + 7][am] = a1v.w;
        *(float4*)&Bs[bk][bn] = *(const float4*)(Wo + (size_t)(k0 + bk) * NCLASS + bn);
        __syncthreads();
        #pragma unroll
        for (int k = 0; k < 16; k++) {
            float a[8];
            *(float4*)&a[0] = *(float4*)&As[k][tr * 8];
            *(float4*)&a[4] = *(float4*)&As[k][tr * 8 + 4];
            ulonglong2 b = *(ulonglong2*)&Bs[k][tc * 4];
            #pragma unroll
            for (int i = 0; i < 8; i++) {
                ull ap = pack2(a[i], a[i]);
                acc[i][0] = fma2(ap, b.x, acc[i][0]);
                acc[i][1] = fma2(ap, b.y, acc[i][1]);
            }
        }
        __syncthreads();
    }
    float* C = g_WhoP + (size_t)kb * N_NODES * NCLASS;
    #pragma unroll
    for (int i = 0; i < 8; i++) {
        ulonglong2 v; v.x = acc[i][0]; v.y = acc[i][1];
        *(ulonglong2*)(C + (size_t)(m0 + tr * 8 + i) * NCLASS + tc * 4) = v;
    }
}

// K3b: reduce split-K, compute g1/g2 + factored exps
__global__ void g12_kernel(const float* __restrict__ ao1, const float* __restrict__ ao2) {
    int gw = (blockIdx.x * blockDim.x + threadIdx.x) >> 5;
    int lane = threadIdx.x & 31;
    if (gw >= N_NODES) return;
    size_t base = (size_t)gw * NCLASS;
    float v1 = 0.f, v2 = 0.f;
    #pragma unroll
    for (int kb = 0; kb < 4; kb++) {
        v1 += g_WhoP[(size_t)kb * N_NODES * NCLASS + base + lane];
        v2 += g_WhoP[(size_t)kb * N_NODES * NCLASS + base + lane + 32];
    }
    g_Who[base + lane] = v1;
    g_Who[base + lane + 32] = v2;
    float s1 = v1 * ao1[lane] + v2 * ao1[lane + 32];
    float s2 = v1 * ao2[lane] + v2 * ao2[lane + 32];
    #pragma unroll
    for (int o = 16; o; o >>= 1) {
        s1 += __shfl_xor_sync(~0u, s1, o);
        s2 += __shfl_xor_sync(~0u, s2, o);
    }
    if (lane == 0) {
        g_g1[gw] = s1;
        g_eo1[gw] = make_float2(__expf(s1), __expf(ALPHA_LRELU * s1));
        g_eo2[gw] = make_float2(__expf(s2), __expf(ALPHA_LRELU * s2));
    }
}

// K4: output attention (exp-free) + elu
__global__ __launch_bounds__(256) void gat_attn2(float* __restrict__ out) {
    __shared__ float VS[64][NCLASS];
    __shared__ float P[32][65];
    __shared__ float l_s[32];
    const int i0 = blockIdx.x * 32;
    const int tid = threadIdx.x, lane = tid & 31, w = tid >> 5;

    float g1v[4]; float2 e1v[4]; float lacc[4];
    #pragma unroll
    for (int rr = 0; rr < 4; rr++) {
        g1v[rr] = g_g1[i0 + w * 4 + rr];
        e1v[rr] = g_eo1[i0 + w * 4 + rr];
        lacc[rr] = 0.f;
    }
    const int tr = tid >> 4, tc = tid & 15;
    ull O[2][2];
    O[0][0] = 0ull; O[0][1] = 0ull; O[1][0] = 0ull; O[1][1] = 0ull;

    for (int j0 = 0; j0 < N_NODES; j0 += 64) {
        #pragma unroll
        for (int t = 0; t < 4; t++) {
            int idx = tid + t * 256;
            int row = idx >> 4, q = (idx & 15) * 4;
            *(float4*)&VS[row][q] = *(const float4*)(g_Who + (size_t)(j0 + row) * NCLASS + q);
        }
        float2 eo2a = g_eo2[j0 + lane];
        float2 eo2b = g_eo2[j0 + 32 + lane];
        float g1a = g_g1[j0 + lane];          // reuse: g2 not stored; recompute s sign via g1? no —
        (void)g1a;
        // need f-sum sign: s = g1_i + g2_j. store g2 in l_s? use __logf? Instead load g2 from global:
        float g2a = __ldg(&((const float*)g_WhoP)[0]);  // placeholder, replaced below
        (void)g2a;
        #pragma unroll
        for (int rr = 0; rr < 4; rr++) {
            int r = w * 4 + rr;
            uint2 bw = *(const uint2*)&g_adjbits[(size_t)(i0 + r) * NWORDS + (j0 >> 5)];
            // sign test via ratio-free compare: s>0  <=>  exp(g1)*exp(g2) > 1  <=>  e1.x*eo2.x > 1
            float pr1 = e1v[rr].x * eo2a.x;
            float pr2 = e1v[rr].x * eo2b.x;
            float p1 = (pr1 > 1.f) ? pr1 : e1v[rr].y * eo2a.y;
            float p2 = (pr2 > 1.f) ? pr2 : e1v[rr].y * eo2b.y;
            p1 = ((bw.x >> lane) & 1u) ? p1 : 0.f;
            p2 = ((bw.y >> lane) & 1u) ? p2 : 0.f;
            P[r][lane] = p1; P[r][lane + 32] = p2;
            lacc[rr] += p1 + p2;
        }
        __syncthreads();
        #pragma unroll 4
        for (int j = 0; j < 64; j++) {
            ulonglong2 wv = *(ulonglong2*)&VS[j][tc * 4];
            float pa = P[tr * 2][j], pb = P[tr * 2 + 1][j];
            ull ppa = pack2(pa, pa), ppb = pack2(pb, pb);
            O[0][0] = fma2(ppa, wv.x, O[0][0]);
            O[0][1] = fma2(ppa, wv.y, O[0][1]);
            O[1][0] = fma2(ppb, wv.x, O[1][0]);
            O[1][1] = fma2(ppb, wv.y, O[1][1]);
        }
        __syncthreads();
    }
    #pragma unroll
    for (int rr = 0; rr < 4; rr++) {
        float v = lacc[rr];
        #pragma unroll
        for (int o = 16; o; o >>= 1) v += __shfl_xor_sync(~0u, v, o);
        if (lane == 0) l_s[w * 4 + rr] = v;
    }
    __syncthreads();
    #pragma unroll
    for (int a = 0; a < 2; a++) {
        int r = tr * 2 + a;
        float inv = 1.f / l_s[r];
        float o[4];
        float2 u0 = unpack2(O[a][0]); o[0] = u0.x * inv; o[1] = u0.y * inv;
        float2 u1 = unpack2(O[a][1]); o[2] = u1.x * inv; o[3] = u1.y * inv;
        #pragma unroll
        for (int b = 0; b < 4; b++) o[b] = (o[b] > 0.f) ? o[b] : expm1f(o[b]);
        *(float4*)(out + (size_t)(i0 + r) * NCLASS + tc * 4) = *(float4*)&o[0];
    }
}

// K5: log_softmax
__global__ void logsoftmax_kernel(float* __restrict__ out) {
    int gw = (blockIdx.x * blockDim.x + threadIdx.x) >> 5;
    int lane = threadIdx.x & 31;
    if (gw >= N_NODES) return;
    float* row = out + (size_t)gw * NCLASS;
    float v1 = row[lane], v2 = row[lane + 32];
    float m = fmaxf(v1, v2);
    #pragma unroll
    for (int o = 16; o; o >>= 1) m = fmaxf(m, __shfl_xor_sync(~0u, m, o));
    float s = __expf(v1 - m) + __expf(v2 - m);
    #pragma unroll
    for (int o = 16; o; o >>= 1) s += __shfl_xor_sync(~0u, s, o);
    float ls = m + logf(s);
    row[lane] = v1 - ls;
    row[lane + 32] = v2 - ls;
}

extern "C" void kernel_launch(void* const* d_in, const int* in_sizes, int n_in,
                              void* d_out, int out_size) {
    const float* x   = (const float*)d_in[0];
    const int*   adj = (const int*)  d_in[1];
    const float* W   = (const float*)d_in[2];
    const float* a1  = (const float*)d_in[3];
    const float* a2  = (const float*)d_in[4];
    const float* Wo  = (const float*)d_in[5];
    const float* ao1 = (const float*)d_in[6];
    const float* ao2 = (const float*)d_in[7];
    float* out = (float*)d_out;

    cudaFuncSetAttribute(gat_attn1, cudaFuncAttributeMaxDynamicSharedMemorySize, SMEM_ATTN1);

    bitpack_kernel<<<(N_NODES * N_NODES) / 256, 256>>>(adj);
    wh_gemm<<<dim3(N_NODES / 128, NHEADS), 256>>>(x, W);
    f12_kernel<<<(NHEADS * N_NODES) / 8, 256>>>(a1, a2);
    gat_attn1<<<dim3(N_NODES / 128, NHEADS), 256, SMEM_ATTN1>>>();
    who_gemm<<<dim3(N_NODES / 128, 4), 256>>>(Wo);
    g12_kernel<<<N_NODES / 8, 256>>>(ao1, ao2);
    gat_attn2<<<N_NODES / 32, 256>>>(out);
    logsoftmax_kernel<<<N_NODES / 8, 256>>>(out);
}

// round 7
// speedup vs baseline: 3.0883x; 1.1492x over previous
#include <cuda_runtime.h>
#include <cuda_bf16.h>
#include <math.h>

#define N_NODES 4096
#define NFEAT   1024
#define NHID    128
#define NHEADS  8
#define NCLASS  64
#define NWORDS  (N_NODES / 32)
#define ALPHA_LRELU 0.2f

__device__ float g_Wh[NHEADS * N_NODES * NHID];
__device__ __nv_bfloat16 g_xhi[N_NODES * NFEAT];
__device__ __nv_bfloat16 g_xlo[N_NODES * NFEAT];
__device__ __nv_bfloat16 g_WThi[NHEADS * NHID * NFEAT];
__device__ __nv_bfloat16 g_WTlo[NHEADS * NHID * NFEAT];
__device__ __nv_bfloat16 g_WhT_hi[NHEADS * NHID * N_NODES];
__device__ __nv_bfloat16 g_WhT_lo[NHEADS * NHID * N_NODES];
__device__ float g_f1[NHEADS * N_NODES];
__device__ float g_f2[NHEADS * N_NODES];
__device__ float2 g_e1[NHEADS * N_NODES];
__device__ float2 g_e2[NHEADS * N_NODES];
__device__ float g_hcat[N_NODES * NHEADS * NHID];
__device__ float g_WhoP[4 * N_NODES * NCLASS];
__device__ float g_Who[N_NODES * NCLASS];
__device__ float g_g1[N_NODES];
__device__ float2 g_eo1[N_NODES];
__device__ float2 g_eo2[N_NODES];
__device__ unsigned g_adjbits[N_NODES * NWORDS];

typedef unsigned long long ull;

__device__ __forceinline__ ull pack2(float lo, float hi) {
    ull r; asm("mov.b64 %0,{%1,%2};" : "=l"(r) : "f"(lo), "f"(hi)); return r;
}
__device__ __forceinline__ float2 unpack2(ull v) {
    float2 f; asm("mov.b64 {%0,%1},%2;" : "=f"(f.x), "=f"(f.y) : "l"(v)); return f;
}
__device__ __forceinline__ ull fma2(ull a, ull b, ull c) {
    ull d; asm("fma.rn.f32x2 %0,%1,%2,%3;" : "=l"(d) : "l"(a), "l"(b), "l"(c)); return d;
}
__device__ __forceinline__ void cp16(void* dst, const void* src) {
    unsigned sa = (unsigned)__cvta_generic_to_shared(dst);
    asm volatile("cp.async.cg.shared.global [%0], [%1], 16;" :: "r"(sa), "l"(src));
}
#define CP_COMMIT() asm volatile("cp.async.commit_group;")
#define CP_WAIT0()  asm volatile("cp.async.wait_group 0;")
#define CP_WAIT1()  asm volatile("cp.async.wait_group 1;")

__device__ __forceinline__ void ldsm4(unsigned* r, unsigned a) {
    asm volatile("ldmatrix.sync.aligned.m8n8.x4.shared.b16 {%0,%1,%2,%3}, [%4];"
                 : "=r"(r[0]), "=r"(r[1]), "=r"(r[2]), "=r"(r[3]) : "r"(a));
}
__device__ __forceinline__ void mma16816(float* d, const unsigned* a, const unsigned* b) {
    asm volatile("mma.sync.aligned.m16n8k16.row.col.f32.bf16.bf16.f32 "
                 "{%0,%1,%2,%3}, {%4,%5,%6,%7}, {%8,%9}, {%0,%1,%2,%3};"
                 : "+f"(d[0]), "+f"(d[1]), "+f"(d[2]), "+f"(d[3])
                 : "r"(a[0]), "r"(a[1]), "r"(a[2]), "r"(a[3]), "r"(b[0]), "r"(b[1]));
}
__device__ __forceinline__ void bfsplit(float v, __nv_bfloat16& h, __nv_bfloat16& l) {
    h = __float2bfloat16(v);
    l = __float2bfloat16(v - __bfloat162float(h));
}

// shared 3-term MMA core: A [128 x 64k] rows at stride 144B, B [128 n x 64k] same.
__device__ __forceinline__ void mma_block(float acc[2][8][4], unsigned AHI, unsigned ALO,
                                          unsigned BHI, unsigned BLO, int mB, int nB, int lane) {
    #pragma unroll
    for (int kt = 0; kt < 4; kt++) {
        const unsigned ka = (kt * 16 + ((lane >> 4) * 8)) * 2;
        const unsigned kb = (kt * 16 + (((lane >> 3) & 1) * 8)) * 2;
        unsigned ah[2][4], al[2][4];
        #pragma unroll
        for (int mi = 0; mi < 2; mi++) {
            unsigned ao = (mB + mi * 16 + (lane & 15)) * 144 + ka;
            ldsm4(ah[mi], AHI + ao);
            ldsm4(al[mi], ALO + ao);
        }
        unsigned bh[4][4], bl[4][4];
        #pragma unroll
        for (int np = 0; np < 4; np++) {
            unsigned bo = (nB + np * 16 + (lane & 7) + ((lane >> 4) * 8)) * 144 + kb;
            ldsm4(bh[np], BHI + bo);
            ldsm4(bl[np], BLO + bo);
        }
        #pragma unroll
        for (int mi = 0; mi < 2; mi++)
            #pragma unroll
            for (int np = 0; np < 4; np++) {
                mma16816(acc[mi][np * 2],     ah[mi], &bh[np][0]);
                mma16816(acc[mi][np * 2],     ah[mi], &bl[np][0]);
                mma16816(acc[mi][np * 2],     al[mi], &bh[np][0]);
                mma16816(acc[mi][np * 2 + 1], ah[mi], &bh[np][2]);
                mma16816(acc[mi][np * 2 + 1], ah[mi], &bl[np][2]);
                mma16816(acc[mi][np * 2 + 1], al[mi], &bh[np][2]);
            }
    }
}

// K0: bit-pack adjacency
__global__ void bitpack_kernel(const int* __restrict__ adj) {
    int e = blockIdx.x * 256 + threadIdx.x;
    unsigned m = __ballot_sync(~0u, adj[e] > 0);
    if ((threadIdx.x & 31) == 0) g_adjbits[e >> 5] = m;
}

// K0b: x -> bf16 hi/lo
__global__ void xcvt_kernel(const float* __restrict__ x) {
    int i = blockIdx.x * 256 + threadIdx.x;   // over N*F/4
    float4 v = ((const float4*)x)[i];
    __nv_bfloat16 h[4], l[4];
    bfsplit(v.x, h[0], l[0]); bfsplit(v.y, h[1], l[1]);
    bfsplit(v.z, h[2], l[2]); bfsplit(v.w, h[3], l[3]);
    *(ull*)&g_xhi[i * 4] = *(ull*)h;
    *(ull*)&g_xlo[i * 4] = *(ull*)l;
}

// K0c: W[h][k][d] -> WT[h][d][k] bf16 hi/lo
__global__ void wcvt_kernel(const float* __restrict__ W) {
    int idx = blockIdx.x * 256 + threadIdx.x;  // over 8*128*1024
    int h = idx >> 17, rem = idx & 131071;
    int d = rem >> 10, k = rem & 1023;
    float v = W[h * (NFEAT * NHID) + k * NHID + d];
    __nv_bfloat16 hb, lb; bfsplit(v, hb, lb);
    g_WThi[idx] = hb; g_WTlo[idx] = lb;
}

// K1: Wh = x @ W via mma.sync bf16 3-term
#define WH_ST 73728
__global__ __launch_bounds__(256) void wh_mma() {
    extern __shared__ __align__(16) char smx[];
    const unsigned sb = (unsigned)__cvta_generic_to_shared(smx);
    const int tid = threadIdx.x, lane = tid & 31, w = tid >> 5;
    const int m0 = blockIdx.x * 128, h = blockIdx.y;
    const int mB = (w & 3) * 32, nB = (w >> 2) * 64;

    float acc[2][8][4];
    #pragma unroll
    for (int mi = 0; mi < 2; mi++)
        #pragma unroll
        for (int nt = 0; nt < 8; nt++)
            #pragma unroll
            for (int e = 0; e < 4; e++) acc[mi][nt][e] = 0.f;

    const __nv_bfloat16* WTh = g_WThi + (size_t)h * NHID * NFEAT;
    const __nv_bfloat16* WTl = g_WTlo + (size_t)h * NHID * NFEAT;

    #define WH_LD(tt, ss) { char* dst = smx + (ss) * WH_ST; size_t ko = (size_t)(tt) * 64; \
        _Pragma("unroll") \
        for (int q = 0; q < 4; q++) { \
            int idx = tid + q * 256; int row = idx >> 3, ch = idx & 7; \
            unsigned off = row * 144 + ch * 16; \
            cp16(dst + off,         g_xhi + (size_t)(m0 + row) * NFEAT + ko + ch * 8); \
            cp16(dst + 18432 + off, g_xlo + (size_t)(m0 + row) * NFEAT + ko + ch * 8); \
            cp16(dst + 36864 + off, WTh + (size_t)row * NFEAT + ko + ch * 8); \
            cp16(dst + 55296 + off, WTl + (size_t)row * NFEAT + ko + ch * 8); } }

    WH_LD(0, 0); CP_COMMIT();
    for (int t = 0; t < 16; t++) {
        const int s = t & 1;
        if (t + 1 < 16) { WH_LD(t + 1, (t + 1) & 1); CP_COMMIT(); CP_WAIT1(); }
        else CP_WAIT0();
        __syncthreads();
        unsigned base = sb + s * WH_ST;
        mma_block(acc, base, base + 18432, base + 36864, base + 55296, mB, nB, lane);
        __syncthreads();
    }
    #pragma unroll
    for (int mi = 0; mi < 2; mi++)
        #pragma unroll
        for (int eh = 0; eh < 2; eh++) {
            int row = mB + mi * 16 + (lane >> 2) + eh * 8;
            float* dst = g_Wh + ((size_t)h * N_NODES + m0 + row) * NHID + nB + (lane & 3) * 2;
            #pragma unroll
            for (int nt = 0; nt < 8; nt++)
                *(float2*)(dst + nt * 8) = make_float2(acc[mi][nt][eh * 2], acc[mi][nt][eh * 2 + 1]);
        }
}

// K1t: Wh -> WhT hi/lo (transposed, bf16)
__global__ void whT_kernel() {
    int idx = blockIdx.x * 256 + threadIdx.x;  // over 8*128*4096
    int h = idx >> 19, rem = idx & 524287;
    int d = rem >> 12, n = rem & 4095;
    float v = g_Wh[((size_t)h * N_NODES + n) * NHID + d];
    __nv_bfloat16 hb, lb; bfsplit(v, hb, lb);
    g_WhT_hi[idx] = hb; g_WhT_lo[idx] = lb;
}

// K1b: f1/f2 + factored exps
__global__ void f12_kernel(const float* __restrict__ a1, const float* __restrict__ a2) {
    int gw = (blockIdx.x * blockDim.x + threadIdx.x) >> 5;
    int lane = threadIdx.x & 31;
    if (gw >= NHEADS * N_NODES) return;
    int h = gw >> 12;
    const float* wh = g_Wh + (size_t)gw * NHID;
    const float* A1 = a1 + h * NHID;
    const float* A2 = a2 + h * NHID;
    float s1 = 0.f, s2 = 0.f;
    #pragma unroll
    for (int d = lane; d < NHID; d += 32) {
        float v = wh[d];
        s1 += v * A1[d]; s2 += v * A2[d];
    }
    #pragma unroll
    for (int o = 16; o; o >>= 1) {
        s1 += __shfl_xor_sync(~0u, s1, o);
        s2 += __shfl_xor_sync(~0u, s2, o);
    }
    if (lane == 0) {
        g_f1[gw] = s1; g_f2[gw] = s2;
        g_e1[gw] = make_float2(__expf(s1), __expf(ALPHA_LRELU * s1));
        g_e2[gw] = make_float2(__expf(s2), __expf(ALPHA_LRELU * s2));
    }
}

// K2: attn layer-1 — exp-free phase A, mma.sync phase B
#define OFF_WS  0
#define OFF_PHI 73728
#define OFF_PLO 92160
#define OFF_LP  110592
#define SMEM_ATTN1 111616

__global__ __launch_bounds__(256) void gat_attn1() {
    extern __shared__ __align__(16) char smx[];
    const unsigned sb = (unsigned)__cvta_generic_to_shared(smx);
    const int tid = threadIdx.x, lane = tid & 31, w = tid >> 5;
    const int h = blockIdx.y, i0 = blockIdx.x * 128;
    const int hN = h * N_NODES;

    const int rg = w & 3, jh = w >> 2;
    const int r = rg * 32 + lane, arow = i0 + r;
    const float f1r = g_f1[hN + arow];
    const float2 e1 = g_e1[hN + arow];
    float lacc = 0.f;

    const int mB = (w & 3) * 32, nB = (w >> 2) * 64;
    float acc[2][8][4];
    #pragma unroll
    for (int mi = 0; mi < 2; mi++)
        #pragma unroll
        for (int nt = 0; nt < 8; nt++)
            #pragma unroll
            for (int e = 0; e < 4; e++) acc[mi][nt][e] = 0.f;

    const __nv_bfloat16* WTh = g_WhT_hi + (size_t)h * NHID * N_NODES;
    const __nv_bfloat16* WTl = g_WhT_lo + (size_t)h * NHID * N_NODES;

    #pragma unroll
    for (int q = 0; q < 4; q++) {
        int idx = tid + q * 256;
        int d = idx >> 3, ch = idx & 7;
        cp16(smx + OFF_WS + d * 144 + ch * 16, WTh + (size_t)d * N_NODES + ch * 8);
        cp16(smx + OFF_WS + 18432 + d * 144 + ch * 16, WTl + (size_t)d * N_NODES + ch * 8);
    }
    CP_COMMIT();

    for (int t = 0; t < 64; t++) {
        const int s = t & 1;
        // phase A: P tile
        {
            unsigned word = g_adjbits[(size_t)arow * NWORDS + t * 2 + jh];
            float f2v = g_f2[hN + t * 64 + jh * 32 + lane];
            float2 e2v = g_e2[hN + t * 64 + jh * 32 + lane];
            unsigned pbase = r * 144 + (jh * 32) * 2;
            #pragma unroll
            for (int jq = 0; jq < 8; jq++) {
                unsigned hv[2], lv[2];
                #pragma unroll
                for (int u = 0; u < 2; u++) {
                    float p[2];
                    #pragma unroll
                    for (int v = 0; v < 2; v++) {
                        int j = jq * 4 + u * 2 + v;
                        float f2j = __shfl_sync(~0u, f2v, j);
                        float ep  = __shfl_sync(~0u, e2v.x, j);
                        float en  = __shfl_sync(~0u, e2v.y, j);
                        float pv = (f1r + f2j > 0.f) ? e1.x * ep : e1.y * en;
                        pv = ((word >> j) & 1u) ? pv : 0.f;
                        lacc += pv;
                        p[v] = pv;
                    }
                    __nv_bfloat16 h0, l0, h1, l1;
                    bfsplit(p[0], h0, l0); bfsplit(p[1], h1, l1);
                    hv[u] = (unsigned)__bfloat16_as_ushort(h0) | ((unsigned)__bfloat16_as_ushort(h1) << 16);
                    lv[u] = (unsigned)__bfloat16_as_ushort(l0) | ((unsigned)__bfloat16_as_ushort(l1) << 16);
                }
                ull hp; asm("mov.b64 %0,{%1,%2};" : "=l"(hp) : "r"(hv[0]), "r"(hv[1]));
                ull lp; asm("mov.b64 %0,{%1,%2};" : "=l"(lp) : "r"(lv[0]), "r"(lv[1]));
                *(ull*)(smx + OFF_PHI + pbase + jq * 8) = hp;
                *(ull*)(smx + OFF_PLO + pbase + jq * 8) = lp;
            }
        }
        if (t + 1 < 64) {
            char* dst = smx + OFF_WS + ((t + 1) & 1) * 36864;
            size_t so = (size_t)(t + 1) * 64;
            #pragma unroll
            for (int q = 0; q < 4; q++) {
                int idx = tid + q * 256;
                int d = idx >> 3, ch = idx & 7;
                cp16(dst + d * 144 + ch * 16, WTh + (size_t)d * N_NODES + so + ch * 8);
                cp16(dst + 18432 + d * 144 + ch * 16, WTl + (size_t)d * N_NODES + so + ch * 8);
            }
            CP_COMMIT();
            CP_WAIT1();
        } else CP_WAIT0();
        __syncthreads();
        unsigned wbase = sb + OFF_WS + s * 36864;
        mma_block(acc, sb + OFF_PHI, sb + OFF_PLO, wbase, wbase + 18432, mB, nB, lane);
        __syncthreads();
    }
    ((float*)(smx + OFF_LP))[jh * 128 + r] = lacc;
    __syncthreads();
    {
        const float* LP = (const float*)(smx + OFF_LP);
        #pragma unroll
        for (int mi = 0; mi < 2; mi++)
            #pragma unroll
            for (int eh = 0; eh < 2; eh++) {
                int row = mB + mi * 16 + (lane >> 2) + eh * 8;
                float inv = 1.f / (LP[row] + LP[128 + row]);
                float* dst = g_hcat + (size_t)(i0 + row) * (NHEADS * NHID) + h * NHID + nB + (lane & 3) * 2;
                #pragma unroll
                for (int nt = 0; nt < 8; nt++) {
                    float v0 = acc[mi][nt][eh * 2] * inv;
                    float v1 = acc[mi][nt][eh * 2 + 1] * inv;
                    v0 = (v0 > 0.f) ? v0 : expm1f(v0);
                    v1 = (v1 > 0.f) ? v1 : expm1f(v1);
                    *(float2*)(dst + nt * 8) = make_float2(v0, v1);
                }
            }
    }
}

// K3: Who = hcat @ Wo (split-K=4, f32x2)
__global__ __launch_bounds__(256) void who_gemm(const float* __restrict__ Wo) {
    __shared__ float As[16][128];
    __shared__ float Bs[16][64];
    const int m0 = blockIdx.x * 128, kb = blockIdx.y;
    const int tid = threadIdx.x;
    const int tr = tid >> 4, tc = tid & 15;
    const int am = tid >> 1, ak = (tid & 1) * 8;
    const int bk = tid >> 4, bn = (tid & 15) * 4;

    ull acc[8][2];
    #pragma unroll
    for (int i = 0; i < 8; i++) { acc[i][0] = 0ull; acc[i][1] = 0ull; }
    const int kbeg = kb * 256, kend = kbeg + 256;
    for (int k0 = kbeg; k0 < kend; k0 += 16) {
        float4 a0 = *(const float4*)(g_hcat + (size_t)(m0 + am) * (NHEADS * NHID) + k0 + ak);
        float4 a1v = *(const float4*)(g_hcat + (size_t)(m0 + am) * (NHEADS * NHID) + k0 + ak + 4);
        As[ak + 0][am] = a0.x; As[ak + 1][am] = a0.y;
        As[ak + 2][am] = a0.z; As[ak + 3][am] = a0.w;
        As[ak + 4][am] = a1v.x; As[ak + 5][am] = a1v.y;
        As[ak + 6][am] = a1v.z; As[ak + 7][am] = a1v.w;
        *(float4*)&Bs[bk][bn] = *(const float4*)(Wo + (size_t)(k0 + bk) * NCLASS + bn);
        __syncthreads();
        #pragma unroll
        for (int k = 0; k < 16; k++) {
            float a[8];
            *(float4*)&a[0] = *(float4*)&As[k][tr * 8];
            *(float4*)&a[4] = *(float4*)&As[k][tr * 8 + 4];
            ulonglong2 b = *(ulonglong2*)&Bs[k][tc * 4];
            #pragma unroll
            for (int i = 0; i < 8; i++) {
                ull ap = pack2(a[i], a[i]);
                acc[i][0] = fma2(ap, b.x, acc[i][0]);
                acc[i][1] = fma2(ap, b.y, acc[i][1]);
            }
        }
        __syncthreads();
    }
    float* C = g_WhoP + (size_t)kb * N_NODES * NCLASS;
    #pragma unroll
    for (int i = 0; i < 8; i++) {
        ulonglong2 v; v.x = acc[i][0]; v.y = acc[i][1];
        *(ulonglong2*)(C + (size_t)(m0 + tr * 8 + i) * NCLASS + tc * 4) = v;
    }
}

// K3b: reduce split-K, g1/g2 exps
__global__ void g12_kernel(const float* __restrict__ ao1, const float* __restrict__ ao2) {
    int gw = (blockIdx.x * blockDim.x + threadIdx.x) >> 5;
    int lane = threadIdx.x & 31;
    if (gw >= N_NODES) return;
    size_t base = (size_t)gw * NCLASS;
    float v1 = 0.f, v2 = 0.f;
    #pragma unroll
    for (int kb = 0; kb < 4; kb++) {
        v1 += g_WhoP[(size_t)kb * N_NODES * NCLASS + base + lane];
        v2 += g_WhoP[(size_t)kb * N_NODES * NCLASS + base + lane + 32];
    }
    g_Who[base + lane] = v1;
    g_Who[base + lane + 32] = v2;
    float s1 = v1 * ao1[lane] + v2 * ao1[lane + 32];
    float s2 = v1 * ao2[lane] + v2 * ao2[lane + 32];
    #pragma unroll
    for (int o = 16; o; o >>= 1) {
        s1 += __shfl_xor_sync(~0u, s1, o);
        s2 += __shfl_xor_sync(~0u, s2, o);
    }
    if (lane == 0) {
        g_g1[gw] = s1;
        g_eo1[gw] = make_float2(__expf(s1), __expf(ALPHA_LRELU * s1));
        g_eo2[gw] = make_float2(__expf(s2), __expf(ALPHA_LRELU * s2));
    }
}

// K4: output attention (exp-free) + elu
__global__ __launch_bounds__(256) void gat_attn2(float* __restrict__ out) {
    __shared__ float VS[64][NCLASS];
    __shared__ float P[32][65];
    __shared__ float l_s[32];
    const int i0 = blockIdx.x * 32;
    const int tid = threadIdx.x, lane = tid & 31, w = tid >> 5;

    float2 e1v[4]; float lacc[4];
    #pragma unroll
    for (int rr = 0; rr < 4; rr++) {
        e1v[rr] = g_eo1[i0 + w * 4 + rr];
        lacc[rr] = 0.f;
    }
    const int tr = tid >> 4, tc = tid & 15;
    ull O[2][2];
    O[0][0] = 0ull; O[0][1] = 0ull; O[1][0] = 0ull; O[1][1] = 0ull;

    for (int j0 = 0; j0 < N_NODES; j0 += 64) {
        #pragma unroll
        for (int t = 0; t < 4; t++) {
            int idx = tid + t * 256;
            int row = idx >> 4, q = (idx & 15) * 4;
            *(float4*)&VS[row][q] = *(const float4*)(g_Who + (size_t)(j0 + row) * NCLASS + q);
        }
        float2 eo2a = g_eo2[j0 + lane];
        float2 eo2b = g_eo2[j0 + 32 + lane];
        #pragma unroll
        for (int rr = 0; rr < 4; rr++) {
            int r = w * 4 + rr;
            uint2 bw = *(const uint2*)&g_adjbits[(size_t)(i0 + r) * NWORDS + (j0 >> 5)];
            float pr1 = e1v[rr].x * eo2a.x;
            float pr2 = e1v[rr].x * eo2b.x;
            float p1 = (pr1 > 1.f) ? pr1 : e1v[rr].y * eo2a.y;
            float p2 = (pr2 > 1.f) ? pr2 : e1v[rr].y * eo2b.y;
            p1 = ((bw.x >> lane) & 1u) ? p1 : 0.f;
            p2 = ((bw.y >> lane) & 1u) ? p2 : 0.f;
            P[r][lane] = p1; P[r][lane + 32] = p2;
            lacc[rr] += p1 + p2;
        }
        __syncthreads();
        #pragma unroll 4
        for (int j = 0; j < 64; j++) {
            ulonglong2 wv = *(ulonglong2*)&VS[j][tc * 4];
            float pa = P[tr * 2][j], pb = P[tr * 2 + 1][j];
            ull ppa = pack2(pa, pa), ppb = pack2(pb, pb);
            O[0][0] = fma2(ppa, wv.x, O[0][0]);
            O[0][1] = fma2(ppa, wv.y, O[0][1]);
            O[1][0] = fma2(ppb, wv.x, O[1][0]);
            O[1][1] = fma2(ppb, wv.y, O[1][1]);
        }
        __syncthreads();
    }
    #pragma unroll
    for (int rr = 0; rr < 4; rr++) {
        float v = lacc[rr];
        #pragma unroll
        for (int o = 16; o; o >>= 1) v += __shfl_xor_sync(~0u, v, o);
        if (lane == 0) l_s[w * 4 + rr] = v;
    }
    __syncthreads();
    #pragma unroll
    for (int a = 0; a < 2; a++) {
        int r = tr * 2 + a;
        float inv = 1.f / l_s[r];
        float o[4];
        float2 u0 = unpack2(O[a][0]); o[0] = u0.x * inv; o[1] = u0.y * inv;
        float2 u1 = unpack2(O[a][1]); o[2] = u1.x * inv; o[3] = u1.y * inv;
        #pragma unroll
        for (int b = 0; b < 4; b++) o[b] = (o[b] > 0.f) ? o[b] : expm1f(o[b]);
        *(float4*)(out + (size_t)(i0 + r) * NCLASS + tc * 4) = *(float4*)&o[0];
    }
}

// K5: log_softmax
__global__ void logsoftmax_kernel(float* __restrict__ out) {
    int gw = (blockIdx.x * blockDim.x + threadIdx.x) >> 5;
    int lane = threadIdx.x & 31;
    if (gw >= N_NODES) return;
    float* row = out + (size_t)gw * NCLASS;
    float v1 = row[lane], v2 = row[lane + 32];
    float m = fmaxf(v1, v2);
    #pragma unroll
    for (int o = 16; o; o >>= 1) m = fmaxf(m, __shfl_xor_sync(~0u, m, o));
    float s = __expf(v1 - m) + __expf(v2 - m);
    #pragma unroll
    for (int o = 16; o; o >>= 1) s += __shfl_xor_sync(~0u, s, o);
    float ls = m + logf(s);
    row[lane] = v1 - ls;
    row[lane + 32] = v2 - ls;
}

extern "C" void kernel_launch(void* const* d_in, const int* in_sizes, int n_in,
                              void* d_out, int out_size) {
    const float* x   = (const float*)d_in[0];
    const int*   adj = (const int*)  d_in[1];
    const float* W   = (const float*)d_in[2];
    const float* a1  = (const float*)d_in[3];
    const float* a2  = (const float*)d_in[4];
    const float* Wo  = (const float*)d_in[5];
    const float* ao1 = (const float*)d_in[6];
    const float* ao2 = (const float*)d_in[7];
    float* out = (float*)d_out;

    cudaFuncSetAttribute(gat_attn1, cudaFuncAttributeMaxDynamicSharedMemorySize, SMEM_ATTN1);
    cudaFuncSetAttribute(wh_mma, cudaFuncAttributeMaxDynamicSharedMemorySize, 2 * WH_ST);

    bitpack_kernel<<<(N_NODES * N_NODES) / 256, 256>>>(adj);
    xcvt_kernel<<<(N_NODES * NFEAT / 4) / 256, 256>>>(x);
    wcvt_kernel<<<(NHEADS * NHID * NFEAT) / 256, 256>>>(W);
    wh_mma<<<dim3(N_NODES / 128, NHEADS), 256, 2 * WH_ST>>>();
    whT_kernel<<<(NHEADS * NHID * N_NODES) / 256, 256>>>();
    f12_kernel<<<(NHEADS * N_NODES) / 8, 256>>>(a1, a2);
    gat_attn1<<<dim3(N_NODES / 128, NHEADS), 256, SMEM_ATTN1>>>();
    who_gemm<<<dim3(N_NODES / 128, 4), 256>>>(Wo);
    g12_kernel<<<N_NODES / 8, 256>>>(ao1, ao2);
    gat_attn2<<<N_NODES / 32, 256>>>(out);
    logsoftmax_kernel<<<N_NODES / 8, 256>>>(out);
}

// round 9
// speedup vs baseline: 3.3360x; 1.0802x over previous
#include <cuda_runtime.h>
#include <cuda_bf16.h>
#include <math.h>

#define N_NODES 4096
#define NFEAT   1024
#define NHID    128
#define NHEADS  8
#define NCLASS  64
#define NWORDS  (N_NODES / 32)
#define ALPHA_LRELU 0.2f

__device__ float g_Wh[NHEADS * N_NODES * NHID];
__device__ __nv_bfloat16 g_xhi[N_NODES * NFEAT];
__device__ __nv_bfloat16 g_xlo[N_NODES * NFEAT];
__device__ __nv_bfloat16 g_WThi[NHEADS * NHID * NFEAT];
__device__ __nv_bfloat16 g_WTlo[NHEADS * NHID * NFEAT];
__device__ __nv_bfloat16 g_WhT_hi[NHEADS * NHID * N_NODES];
__device__ __nv_bfloat16 g_WhT_lo[NHEADS * NHID * N_NODES];
__device__ float g_f1[NHEADS * N_NODES];
__device__ float g_f2[NHEADS * N_NODES];
__device__ float2 g_e1[NHEADS * N_NODES];
__device__ float2 g_e2[NHEADS * N_NODES];
__device__ float g_hcat[N_NODES * NHEADS * NHID];
__device__ float g_WhoP[4 * N_NODES * NCLASS];
__device__ float g_Who[N_NODES * NCLASS];
__device__ float g_g1[N_NODES];
__device__ float2 g_eo1[N_NODES];
__device__ float2 g_eo2[N_NODES];
__device__ unsigned g_adjbits[N_NODES * NWORDS];

typedef unsigned long long ull;

__device__ __forceinline__ ull pack2(float lo, float hi) {
    ull r; asm("mov.b64 %0,{%1,%2};" : "=l"(r) : "f"(lo), "f"(hi)); return r;
}
__device__ __forceinline__ float2 unpack2(ull v) {
    float2 f; asm("mov.b64 {%0,%1},%2;" : "=f"(f.x), "=f"(f.y) : "l"(v)); return f;
}
__device__ __forceinline__ ull fma2(ull a, ull b, ull c) {
    ull d; asm("fma.rn.f32x2 %0,%1,%2,%3;" : "=l"(d) : "l"(a), "l"(b), "l"(c)); return d;
}
__device__ __forceinline__ void cp16(void* dst, const void* src) {
    unsigned sa = (unsigned)__cvta_generic_to_shared(dst);
    asm volatile("cp.async.cg.shared.global [%0], [%1], 16;" :: "r"(sa), "l"(src));
}
#define CP_COMMIT() asm volatile("cp.async.commit_group;")
#define CP_WAIT0()  asm volatile("cp.async.wait_group 0;")
#define CP_WAIT1()  asm volatile("cp.async.wait_group 1;")

__device__ __forceinline__ void ldsm4(unsigned* r, unsigned a) {
    asm volatile("ldmatrix.sync.aligned.m8n8.x4.shared.b16 {%0,%1,%2,%3}, [%4];"
                 : "=r"(r[0]), "=r"(r[1]), "=r"(r[2]), "=r"(r[3]) : "r"(a));
}
__device__ __forceinline__ void mma16816(float* d, const unsigned* a, const unsigned* b) {
    asm volatile("mma.sync.aligned.m16n8k16.row.col.f32.bf16.bf16.f32 "
                 "{%0,%1,%2,%3}, {%4,%5,%6,%7}, {%8,%9}, {%0,%1,%2,%3};"
                 : "+f"(d[0]), "+f"(d[1]), "+f"(d[2]), "+f"(d[3])
                 : "r"(a[0]), "r"(a[1]), "r"(a[2]), "r"(a[3]), "r"(b[0]), "r"(b[1]));
}
__device__ __forceinline__ void bfsplit(float v, __nv_bfloat16& h, __nv_bfloat16& l) {
    h = __float2bfloat16(v);
    l = __float2bfloat16(v - __bfloat162float(h));
}

// shared 3-term MMA core: A [128 x 64k] rows at stride 144B, B [128 n x 64k] same.
__device__ __forceinline__ void mma_block(float acc[2][8][4], unsigned AHI, unsigned ALO,
                                          unsigned BHI, unsigned BLO, int mB, int nB, int lane) {
    #pragma unroll
    for (int kt = 0; kt < 4; kt++) {
        const unsigned ka = (kt * 16 + ((lane >> 4) * 8)) * 2;
        const unsigned kb = (kt * 16 + (((lane >> 3) & 1) * 8)) * 2;
        unsigned ah[2][4], al[2][4];
        #pragma unroll
        for (int mi = 0; mi < 2; mi++) {
            unsigned ao = (mB + mi * 16 + (lane & 15)) * 144 + ka;
            ldsm4(ah[mi], AHI + ao);
            ldsm4(al[mi], ALO + ao);
        }
        unsigned bh[4][4], bl[4][4];
        #pragma unroll
        for (int np = 0; np < 4; np++) {
            unsigned bo = (nB + np * 16 + (lane & 7) + ((lane >> 4) * 8)) * 144 + kb;
            ldsm4(bh[np], BHI + bo);
            ldsm4(bl[np], BLO + bo);
        }
        #pragma unroll
        for (int mi = 0; mi < 2; mi++)
            #pragma unroll
            for (int np = 0; np < 4; np++) {
                mma16816(acc[mi][np * 2],     ah[mi], &bh[np][0]);
                mma16816(acc[mi][np * 2],     ah[mi], &bl[np][0]);
                mma16816(acc[mi][np * 2],     al[mi], &bh[np][0]);
                mma16816(acc[mi][np * 2 + 1], ah[mi], &bh[np][2]);
                mma16816(acc[mi][np * 2 + 1], ah[mi], &bl[np][2]);
                mma16816(acc[mi][np * 2 + 1], al[mi], &bh[np][2]);
            }
    }
}

// K0: bit-pack adjacency (4 elems/thread, shfl nibble merge)
__global__ void bitpack_kernel(const int* __restrict__ adj) {
    int idx = blockIdx.x * 256 + threadIdx.x;
    int4 v = ((const int4*)adj)[idx];
    unsigned b = (v.x > 0 ? 1u : 0u) | (v.y > 0 ? 2u : 0u)
               | (v.z > 0 ? 4u : 0u) | (v.w > 0 ? 8u : 0u);
    b |= __shfl_xor_sync(~0u, b, 1) << 4;
    b |= __shfl_xor_sync(~0u, b, 2) << 8;
    b |= __shfl_xor_sync(~0u, b, 4) << 16;
    if ((threadIdx.x & 7) == 0) g_adjbits[idx >> 3] = b;
}

// K0b: x -> bf16 hi/lo
__global__ void xcvt_kernel(const float* __restrict__ x) {
    int i = blockIdx.x * 256 + threadIdx.x;
    float4 v = ((const float4*)x)[i];
    __nv_bfloat16 h[4], l[4];
    bfsplit(v.x, h[0], l[0]); bfsplit(v.y, h[1], l[1]);
    bfsplit(v.z, h[2], l[2]); bfsplit(v.w, h[3], l[3]);
    *(ull*)&g_xhi[i * 4] = *(ull*)h;
    *(ull*)&g_xlo[i * 4] = *(ull*)l;
}

// K0c: W[h][k][d] -> WT[h][d][k] bf16 hi/lo
__global__ void wcvt_kernel(const float* __restrict__ W) {
    int idx = blockIdx.x * 256 + threadIdx.x;
    int h = idx >> 17, rem = idx & 131071;
    int d = rem >> 10, k = rem & 1023;
    float v = W[h * (NFEAT * NHID) + k * NHID + d];
    __nv_bfloat16 hb, lb; bfsplit(v, hb, lb);
    g_WThi[idx] = hb; g_WTlo[idx] = lb;
}

// K1: Wh = x @ W via mma.sync bf16 3-term
#define WH_ST 73728
__global__ __launch_bounds__(256) void wh_mma() {
    extern __shared__ __align__(16) char smx[];
    const unsigned sb = (unsigned)__cvta_generic_to_shared(smx);
    const int tid = threadIdx.x, lane = tid & 31, w = tid >> 5;
    const int m0 = blockIdx.x * 128, h = blockIdx.y;
    const int mB = (w & 3) * 32, nB = (w >> 2) * 64;

    float acc[2][8][4];
    #pragma unroll
    for (int mi = 0; mi < 2; mi++)
        #pragma unroll
        for (int nt = 0; nt < 8; nt++)
            #pragma unroll
            for (int e = 0; e < 4; e++) acc[mi][nt][e] = 0.f;

    const __nv_bfloat16* WTh = g_WThi + (size_t)h * NHID * NFEAT;
    const __nv_bfloat16* WTl = g_WTlo + (size_t)h * NHID * NFEAT;

    #define WH_LD(tt, ss) { char* dst = smx + (ss) * WH_ST; size_t ko = (size_t)(tt) * 64; \
        _Pragma("unroll") \
        for (int q = 0; q < 4; q++) { \
            int idx = tid + q * 256; int row = idx >> 3, ch = idx & 7; \
            unsigned off = row * 144 + ch * 16; \
            cp16(dst + off,         g_xhi + (size_t)(m0 + row) * NFEAT + ko + ch * 8); \
            cp16(dst + 18432 + off, g_xlo + (size_t)(m0 + row) * NFEAT + ko + ch * 8); \
            cp16(dst + 36864 + off, WTh + (size_t)row * NFEAT + ko + ch * 8); \
            cp16(dst + 55296 + off, WTl + (size_t)row * NFEAT + ko + ch * 8); } }

    WH_LD(0, 0); CP_COMMIT();
    for (int t = 0; t < 16; t++) {
        const int s = t & 1;
        if (t + 1 < 16) { WH_LD(t + 1, (t + 1) & 1); CP_COMMIT(); CP_WAIT1(); }
        else CP_WAIT0();
        __syncthreads();
        unsigned base = sb + s * WH_ST;
        mma_block(acc, base, base + 18432, base + 36864, base + 55296, mB, nB, lane);
        __syncthreads();
    }
    #pragma unroll
    for (int mi = 0; mi < 2; mi++)
        #pragma unroll
        for (int eh = 0; eh < 2; eh++) {
            int row = mB + mi * 16 + (lane >> 2) + eh * 8;
            float* dst = g_Wh + ((size_t)h * N_NODES + m0 + row) * NHID + nB + (lane & 3) * 2;
            #pragma unroll
            for (int nt = 0; nt < 8; nt++)
                *(float2*)(dst + nt * 8) = make_float2(acc[mi][nt][eh * 2], acc[mi][nt][eh * 2 + 1]);
        }
}

// K1t: Wh -> WhT hi/lo (coalesced tile transpose)
__global__ __launch_bounds__(256) void whT_kernel() {
    __shared__ float tile[64][65];
    const int h = blockIdx.z, d0 = blockIdx.y * 64, n0 = blockIdx.x * 64;
    const int tid = threadIdx.x;
    #pragma unroll
    for (int q = 0; q < 16; q++) {
        int lin = tid + q * 256;
        int row = lin >> 6, col = lin & 63;     // row = n_loc, col = d_loc
        tile[row][col] = g_Wh[((size_t)h * N_NODES + n0 + row) * NHID + d0 + col];
    }
    __syncthreads();
    #pragma unroll
    for (int q = 0; q < 8; q++) {
        int lin = tid + q * 256;
        int drow = lin >> 5, np = (lin & 31) * 2;
        float v0 = tile[np][drow], v1 = tile[np + 1][drow];
        __nv_bfloat16 h0, l0, h1, l1;
        bfsplit(v0, h0, l0); bfsplit(v1, h1, l1);
        unsigned hw = (unsigned)__bfloat16_as_ushort(h0) | ((unsigned)__bfloat16_as_ushort(h1) << 16);
        unsigned lw = (unsigned)__bfloat16_as_ushort(l0) | ((unsigned)__bfloat16_as_ushort(l1) << 16);
        size_t o = ((size_t)h * NHID + d0 + drow) * N_NODES + n0 + np;
        *(unsigned*)&g_WhT_hi[o] = hw;
        *(unsigned*)&g_WhT_lo[o] = lw;
    }
}

// K1b: f1/f2 + factored exps
__global__ void f12_kernel(const float* __restrict__ a1, const float* __restrict__ a2) {
    int gw = (blockIdx.x * blockDim.x + threadIdx.x) >> 5;
    int lane = threadIdx.x & 31;
    if (gw >= NHEADS * N_NODES) return;
    int h = gw >> 12;
    const float* wh = g_Wh + (size_t)gw * NHID;
    const float* A1 = a1 + h * NHID;
    const float* A2 = a2 + h * NHID;
    float s1 = 0.f, s2 = 0.f;
    #pragma unroll
    for (int d = lane; d < NHID; d += 32) {
        float v = wh[d];
        s1 += v * A1[d]; s2 += v * A2[d];
    }
    #pragma unroll
    for (int o = 16; o; o >>= 1) {
        s1 += __shfl_xor_sync(~0u, s1, o);
        s2 += __shfl_xor_sync(~0u, s2, o);
    }
    if (lane == 0) {
        g_f1[gw] = s1; g_f2[gw] = s2;
        g_e1[gw] = make_float2(__expf(s1), __expf(ALPHA_LRELU * s1));
        g_e2[gw] = make_float2(__expf(s2), __expf(ALPHA_LRELU * s2));
    }
}

// K2: attn layer-1 — pipelined: MMA(t) || phaseA(t+1), one sync per tile
#define OFF_WS  0
#define OFF_P   73728
#define OFF_LP  147456
#define SMEM_ATTN1 148480

__global__ __launch_bounds__(256) void gat_attn1() {
    extern __shared__ __align__(16) char smx[];
    const unsigned sb = (unsigned)__cvta_generic_to_shared(smx);
    const int tid = threadIdx.x, lane = tid & 31, w = tid >> 5;
    const int h = blockIdx.y, i0 = blockIdx.x * 128;
    const int hN = h * N_NODES;

    const int rg = w & 3, jh = w >> 2;
    const int r = rg * 32 + lane, arow = i0 + r;
    const float f1r = g_f1[hN + arow];
    const float2 e1 = g_e1[hN + arow];
    float lacc = 0.f;

    const int mB = (w & 3) * 32, nB = (w >> 2) * 64;
    float acc[2][8][4];
    #pragma unroll
    for (int mi = 0; mi < 2; mi++)
        #pragma unroll
        for (int nt = 0; nt < 8; nt++)
            #pragma unroll
            for (int e = 0; e < 4; e++) acc[mi][nt][e] = 0.f;

    const __nv_bfloat16* WTh = g_WhT_hi + (size_t)h * NHID * N_NODES;
    const __nv_bfloat16* WTl = g_WhT_lo + (size_t)h * NHID * N_NODES;

    #define W_LD(tt, ss) { char* dst = smx + OFF_WS + (ss) * 36864; size_t so = (size_t)(tt) * 64; \
        _Pragma("unroll") \
        for (int q = 0; q < 4; q++) { \
            int idx = tid + q * 256; int d = idx >> 3, ch = idx & 7; \
            cp16(dst + d * 144 + ch * 16,         WTh + (size_t)d * N_NODES + so + ch * 8); \
            cp16(dst + 18432 + d * 144 + ch * 16, WTl + (size_t)d * N_NODES + so + ch * 8); } }

    #define P_GEN(tt, ss) { char* pstg = smx + OFF_P + (ss) * 36864; \
        unsigned word = g_adjbits[(size_t)arow * NWORDS + (tt) * 2 + jh]; \
        float f2v = g_f2[hN + (tt) * 64 + jh * 32 + lane]; \
        float2 e2v = g_e2[hN + (tt) * 64 + jh * 32 + lane]; \
        unsigned pbase = r * 144 + (jh * 32) * 2; \
        _Pragma("unroll") \
        for (int jq = 0; jq < 8; jq++) { \
            unsigned hv[2], lv[2]; \
            _Pragma("unroll") \
            for (int u = 0; u < 2; u++) { \
                float p[2]; \
                _Pragma("unroll") \
                for (int vv = 0; vv < 2; vv++) { \
                    int j = jq * 4 + u * 2 + vv; \
                    float f2j = __shfl_sync(~0u, f2v, j); \
                    float ep  = __shfl_sync(~0u, e2v.x, j); \
                    float en  = __shfl_sync(~0u, e2v.y, j); \
                    float pv = (f1r + f2j > 0.f) ? e1.x * ep : e1.y * en; \
                    pv = ((word >> j) & 1u) ? pv : 0.f; \
                    lacc += pv; \
                    p[vv] = pv; \
                } \
                __nv_bfloat16 h0, l0, h1, l1; \
                bfsplit(p[0], h0, l0); bfsplit(p[1], h1, l1); \
                hv[u] = (unsigned)__bfloat16_as_ushort(h0) | ((unsigned)__bfloat16_as_ushort(h1) << 16); \
                lv[u] = (unsigned)__bfloat16_as_ushort(l0) | ((unsigned)__bfloat16_as_ushort(l1) << 16); \
            } \
            ull hp; asm("mov.b64 %0,{%1,%2};" : "=l"(hp) : "r"(hv[0]), "r"(hv[1])); \
            ull lp; asm("mov.b64 %0,{%1,%2};" : "=l"(lp) : "r"(lv[0]), "r"(lv[1])); \
            *(ull*)(pstg + pbase + jq * 8) = hp; \
            *(ull*)(pstg + 18432 + pbase + jq * 8) = lp; \
        } }

    // prologue: W(0), W(1) in flight; P(0) generated
    W_LD(0, 0); CP_COMMIT();
    W_LD(1, 1); CP_COMMIT();
    P_GEN(0, 0);
    CP_WAIT1();        // W(0) arrived
    __syncthreads();   // P(0) visible

    for (int t = 0; t < 64; t++) {
        const int s = t & 1;
        unsigned wb = sb + OFF_WS + s * 36864;
        unsigned pb = sb + OFF_P + s * 36864;
        mma_block(acc, pb, pb + 18432, wb, wb + 18432, mB, nB, lane);
        if (t + 1 < 64) P_GEN(t + 1, (t + 1) & 1);
        __syncthreads();
        if (t + 2 < 64) { W_LD(t + 2, s); CP_COMMIT(); CP_WAIT1(); }
        else CP_WAIT0();
    }
    ((float*)(smx + OFF_LP))[jh * 128 + r] = lacc;
    __syncthreads();
    {
        const float* LP = (const float*)(smx + OFF_LP);
        #pragma unroll
        for (int mi = 0; mi < 2; mi++)
            #pragma unroll
            for (int eh = 0; eh < 2; eh++) {
                int row = mB + mi * 16 + (lane >> 2) + eh * 8;
                float inv = 1.f / (LP[row] + LP[128 + row]);
                float* dst = g_hcat + (size_t)(i0 + row) * (NHEADS * NHID) + h * NHID + nB + (lane & 3) * 2;
                #pragma unroll
                for (int nt = 0; nt < 8; nt++) {
                    float v0 = acc[mi][nt][eh * 2] * inv;
                    float v1 = acc[mi][nt][eh * 2 + 1] * inv;
                    v0 = (v0 > 0.f) ? v0 : expm1f(v0);
                    v1 = (v1 > 0.f) ? v1 : expm1f(v1);
                    *(float2*)(dst + nt * 8) = make_float2(v0, v1);
                }
            }
    }
}

// K3: Who = hcat @ Wo (split-K=4, f32x2)
__global__ __launch_bounds__(256) void who_gemm(const float* __restrict__ Wo) {
    __shared__ float As[16][128];
    __shared__ float Bs[16][64];
    const int m0 = blockIdx.x * 128, kb = blockIdx.y;
    const int tid = threadIdx.x;
    const int tr = tid >> 4, tc = tid & 15;
    const int am = tid >> 1, ak = (tid & 1) * 8;
    const int bk = tid >> 4, bn = (tid & 15) * 4;

    ull acc[8][2];
    #pragma unroll
    for (int i = 0; i < 8; i++) { acc[i][0] = 0ull; acc[i][1] = 0ull; }
    const int kbeg = kb * 256, kend = kbeg + 256;
    for (int k0 = kbeg; k0 < kend; k0 += 16) {
        float4 a0 = *(const float4*)(g_hcat + (size_t)(m0 + am) * (NHEADS * NHID) + k0 + ak);
        float4 a1v = *(const float4*)(g_hcat + (size_t)(m0 + am) * (NHEADS * NHID) + k0 + ak + 4);
        As[ak + 0][am] = a0.x; As[ak + 1][am] = a0.y;
        As[ak + 2][am] = a0.z; As[ak + 3][am] = a0.w;
        As[ak + 4][am] = a1v.x; As[ak + 5][am] = a1v.y;
        As[ak + 6][am] = a1v.z; As[ak + 7][am] = a1v.w;
        *(float4*)&Bs[bk][bn] = *(const float4*)(Wo + (size_t)(k0 + bk) * NCLASS + bn);
        __syncthreads();
        #pragma unroll
        for (int k = 0; k < 16; k++) {
            float a[8];
            *(float4*)&a[0] = *(float4*)&As[k][tr * 8];
            *(float4*)&a[4] = *(float4*)&As[k][tr * 8 + 4];
            ulonglong2 b = *(ulonglong2*)&Bs[k][tc * 4];
            #pragma unroll
            for (int i = 0; i < 8; i++) {
                ull ap = pack2(a[i], a[i]);
                acc[i][0] = fma2(ap, b.x, acc[i][0]);
                acc[i][1] = fma2(ap, b.y, acc[i][1]);
            }
        }
        __syncthreads();
    }
    float* C = g_WhoP + (size_t)kb * N_NODES * NCLASS;
    #pragma unroll
    for (int i = 0; i < 8; i++) {
        ulonglong2 v; v.x = acc[i][0]; v.y = acc[i][1];
        *(ulonglong2*)(C + (size_t)(m0 + tr * 8 + i) * NCLASS + tc * 4) = v;
    }
}

// K3b: reduce split-K, g1/g2 exps
__global__ void g12_kernel(const float* __restrict__ ao1, const float* __restrict__ ao2) {
    int gw = (blockIdx.x * blockDim.x + threadIdx.x) >> 5;
    int lane = threadIdx.x & 31;
    if (gw >= N_NODES) return;
    size_t base = (size_t)gw * NCLASS;
    float v1 = 0.f, v2 = 0.f;
    #pragma unroll
    for (int kb = 0; kb < 4; kb++) {
        v1 += g_WhoP[(size_t)kb * N_NODES * NCLASS + base + lane];
        v2 += g_WhoP[(size_t)kb * N_NODES * NCLASS + base + lane + 32];
    }
    g_Who[base + lane] = v1;
    g_Who[base + lane + 32] = v2;
    float s1 = v1 * ao1[lane] + v2 * ao1[lane + 32];
    float s2 = v1 * ao2[lane] + v2 * ao2[lane + 32];
    #pragma unroll
    for (int o = 16; o; o >>= 1) {
        s1 += __shfl_xor_sync(~0u, s1, o);
        s2 += __shfl_xor_sync(~0u, s2, o);
    }
    if (lane == 0) {
        g_g1[gw] = s1;
        g_eo1[gw] = make_float2(__expf(s1), __expf(ALPHA_LRELU * s1));
        g_eo2[gw] = make_float2(__expf(s2), __expf(ALPHA_LRELU * s2));
    }
}

// K4: output attention — pipelined: FMA2(t) || {VS,P}(t+1), one sync per tile
__global__ __launch_bounds__(256) void gat_attn2(float* __restrict__ out) {
    __shared__ float VS[2][64][NCLASS];
    __shared__ float P[2][32][65];
    __shared__ float l_s[32];
    const int i0 = blockIdx.x * 32;
    const int tid = threadIdx.x, lane = tid & 31, w = tid >> 5;

    float2 e1v[4]; float lacc[4];
    #pragma unroll
    for (int rr = 0; rr < 4; rr++) {
        e1v[rr] = g_eo1[i0 + w * 4 + rr];
        lacc[rr] = 0.f;
    }
    const int tr = tid >> 4, tc = tid & 15;
    ull O[2][2];
    O[0][0] = 0ull; O[0][1] = 0ull; O[1][0] = 0ull; O[1][1] = 0ull;

    #define VS_LD(tt, ss) { _Pragma("unroll") for (int q = 0; q < 4; q++) { \
        int idx = tid + q * 256; int row = idx >> 4, c = (idx & 15) * 4; \
        *(float4*)&VS[ss][row][c] = *(const float4*)(g_Who + (size_t)((tt) * 64 + row) * NCLASS + c); } }

    #define P_GEN2(tt, ss) { \
        float2 eo2a = g_eo2[(tt) * 64 + lane]; \
        float2 eo2b = g_eo2[(tt) * 64 + 32 + lane]; \
        _Pragma("unroll") for (int rr = 0; rr < 4; rr++) { \
            int rq = w * 4 + rr; \
            uint2 bw = *(const uint2*)&g_adjbits[(size_t)(i0 + rq) * NWORDS + (tt) * 2]; \
            float pr1 = e1v[rr].x * eo2a.x; \
            float pr2 = e1v[rr].x * eo2b.x; \
            float p1 = (pr1 > 1.f) ? pr1 : e1v[rr].y * eo2a.y; \
            float p2 = (pr2 > 1.f) ? pr2 : e1v[rr].y * eo2b.y; \
            p1 = ((bw.x >> lane) & 1u) ? p1 : 0.f; \
            p2 = ((bw.y >> lane) & 1u) ? p2 : 0.f; \
            P[ss][rq][lane] = p1; P[ss][rq][lane + 32] = p2; \
            lacc[rr] += p1 + p2; } }

    VS_LD(0, 0); P_GEN2(0, 0);
    __syncthreads();
    for (int t = 0; t < 64; t++) {
        const int s = t & 1;
        #pragma unroll 4
        for (int j = 0; j < 64; j++) {
            ulonglong2 wv = *(ulonglong2*)&VS[s][j][tc * 4];
            float pa = P[s][tr * 2][j], pb = P[s][tr * 2 + 1][j];
            ull ppa = pack2(pa, pa), ppb = pack2(pb, pb);
            O[0][0] = fma2(ppa, wv.x, O[0][0]);
            O[0][1] = fma2(ppa, wv.y, O[0][1]);
            O[1][0] = fma2(ppb, wv.x, O[1][0]);
            O[1][1] = fma2(ppb, wv.y, O[1][1]);
        }
        if (t + 1 < 64) { VS_LD(t + 1, (t + 1) & 1); P_GEN2(t + 1, (t + 1) & 1); }
        __syncthreads();
    }
    #pragma unroll
    for (int rr = 0; rr < 4; rr++) {
        float v = lacc[rr];
        #pragma unroll
        for (int o = 16; o; o >>= 1) v += __shfl_xor_sync(~0u, v, o);
        if (lane == 0) l_s[w * 4 + rr] = v;
    }
    __syncthreads();
    #pragma unroll
    for (int a = 0; a < 2; a++) {
        int rq = tr * 2 + a;
        float inv = 1.f / l_s[rq];
        float o[4];
        float2 u0 = unpack2(O[a][0]); o[0] = u0.x * inv; o[1] = u0.y * inv;
        float2 u1 = unpack2(O[a][1]); o[2] = u1.x * inv; o[3] = u1.y * inv;
        #pragma unroll
        for (int b = 0; b < 4; b++) o[b] = (o[b] > 0.f) ? o[b] : expm1f(o[b]);
        *(float4*)(out + (size_t)(i0 + rq) * NCLASS + tc * 4) = *(float4*)&o[0];
    }
}

// K5: log_softmax
__global__ void logsoftmax_kernel(float* __restrict__ out) {
    int gw = (blockIdx.x * blockDim.x + threadIdx.x) >> 5;
    int lane = threadIdx.x & 31;
    if (gw >= N_NODES) return;
    float* row = out + (size_t)gw * NCLASS;
    float v1 = row[lane], v2 = row[lane + 32];
    float m = fmaxf(v1, v2);
    #pragma unroll
    for (int o = 16; o; o >>= 1) m = fmaxf(m, __shfl_xor_sync(~0u, m, o));
    float s = __expf(v1 - m) + __expf(v2 - m);
    #pragma unroll
    for (int o = 16; o; o >>= 1) s += __shfl_xor_sync(~0u, s, o);
    float ls = m + logf(s);
    row[lane] = v1 - ls;
    row[lane + 32] = v2 - ls;
}

extern "C" void kernel_launch(void* const* d_in, const int* in_sizes, int n_in,
                              void* d_out, int out_size) {
    const float* x   = (const float*)d_in[0];
    const int*   adj = (const int*)  d_in[1];
    const float* W   = (const float*)d_in[2];
    const float* a1  = (const float*)d_in[3];
    const float* a2  = (const float*)d_in[4];
    const float* Wo  = (const float*)d_in[5];
    const float* ao1 = (const float*)d_in[6];
    const float* ao2 = (const float*)d_in[7];
    float* out = (float*)d_out;

    cudaFuncSetAttribute(gat_attn1, cudaFuncAttributeMaxDynamicSharedMemorySize, SMEM_ATTN1);
    cudaFuncSetAttribute(wh_mma, cudaFuncAttributeMaxDynamicSharedMemorySize, 2 * WH_ST);

    bitpack_kernel<<<(N_NODES * N_NODES / 4) / 256, 256>>>(adj);
    xcvt_kernel<<<(N_NODES * NFEAT / 4) / 256, 256>>>(x);
    wcvt_kernel<<<(NHEADS * NHID * NFEAT) / 256, 256>>>(W);
    wh_mma<<<dim3(N_NODES / 128, NHEADS), 256, 2 * WH_ST>>>();
    whT_kernel<<<dim3(N_NODES / 64, NHID / 64, NHEADS), 256>>>();
    f12_kernel<<<(NHEADS * N_NODES) / 8, 256>>>(a1, a2);
    gat_attn1<<<dim3(N_NODES / 128, NHEADS), 256, SMEM_ATTN1>>>();
    who_gemm<<<dim3(N_NODES / 128, 4), 256>>>(Wo);
    g12_kernel<<<N_NODES / 8, 256>>>(ao1, ao2);
    gat_attn2<<<N_NODES / 32, 256>>>(out);
    logsoftmax_kernel<<<N_NODES / 8, 256>>>(out);
}